// round 9
// baseline (speedup 1.0000x reference)
#include <cuda_runtime.h>
#include <cuda_bf16.h>
#include <cstdint>

typedef __nv_bfloat16 bf16;
typedef unsigned long long u64;

#define NN 128
#define PP 256
#define DD 128
#define HD 16
#define ROWS (NN*PP)      // 32768
#define HIDDEN 2048

// ---------------- scratch (device globals; no cudaMalloc allowed) ----------
__device__ bf16  g_xhi[(size_t)ROWS * DD],    g_xlo[(size_t)ROWS * DD];
__device__ float g_y1 [(size_t)ROWS * 768];
__device__ bf16  g_thi[(size_t)ROWS * 256],   g_tlo[(size_t)ROWS * 256];
__device__ float g_y2 [(size_t)ROWS * 768];
__device__ bf16  g_pahi[(size_t)ROWS * 256],  g_palo[(size_t)ROWS * 256];
__device__ bf16  g_hhi[(size_t)ROWS * HIDDEN], g_hlo[(size_t)ROWS * HIDDEN];
// transposed split weights: Bt[n][k]
__device__ bf16  g_w1t_hi[768 * 128],   g_w1t_lo[768 * 128];
__device__ bf16  g_w2t_hi[768 * 256],   g_w2t_lo[768 * 256];
__device__ bf16  g_f1t_hi[2048 * 256],  g_f1t_lo[2048 * 256];
__device__ bf16  g_f2t_hi[256 * 2048],  g_f2t_lo[256 * 2048];

// ---------------- helpers ---------------------------------------------------
__device__ __forceinline__ uint32_t smem_u32(const void* p) {
    uint32_t a;
    asm("{ .reg .u64 t; cvta.to.shared.u64 t, %1; cvt.u32.u64 %0, t; }"
        : "=r"(a) : "l"(p));
    return a;
}
__device__ __forceinline__ void cp16(uint32_t dst, const void* src) {
    asm volatile("cp.async.cg.shared.global [%0], [%1], 16;"
                 :: "r"(dst), "l"(src) : "memory");
}
__device__ __forceinline__ void mma_bf16(float* d, const uint32_t* a, const uint32_t* b) {
    asm volatile(
        "mma.sync.aligned.m16n8k16.row.col.f32.bf16.bf16.f32 "
        "{%0,%1,%2,%3}, {%4,%5,%6,%7}, {%8,%9}, {%0,%1,%2,%3};"
        : "+f"(d[0]), "+f"(d[1]), "+f"(d[2]), "+f"(d[3])
        : "r"(a[0]), "r"(a[1]), "r"(a[2]), "r"(a[3]), "r"(b[0]), "r"(b[1]));
}
__device__ __forceinline__ void ldsm4(uint32_t& r0, uint32_t& r1, uint32_t& r2,
                                      uint32_t& r3, uint32_t addr) {
    asm volatile("ldmatrix.sync.aligned.m8n8.x4.shared.b16 {%0,%1,%2,%3}, [%4];"
                 : "=r"(r0), "=r"(r1), "=r"(r2), "=r"(r3) : "r"(addr));
}
// packed f32x2 (Blackwell FFMA2 path)
__device__ __forceinline__ u64 fma2(u64 a, u64 b, u64 c) {
    u64 d; asm("fma.rn.f32x2 %0, %1, %2, %3;" : "=l"(d) : "l"(a), "l"(b), "l"(c));
    return d;
}
__device__ __forceinline__ u64 add2(u64 a, u64 b) {
    u64 d; asm("add.rn.f32x2 %0, %1, %2;" : "=l"(d) : "l"(a), "l"(b));
    return d;
}
__device__ __forceinline__ u64 pack2(float a, float b) {
    u64 d; asm("mov.b64 %0, {%1, %2};" : "=l"(d)
               : "r"(__float_as_uint(a)), "r"(__float_as_uint(b)));
    return d;
}
__device__ __forceinline__ void unpack2(u64 v, float& a, float& b) {
    uint32_t x, y;
    asm("mov.b64 {%0, %1}, %2;" : "=r"(x), "=r"(y) : "l"(v));
    a = __uint_as_float(x); b = __uint_as_float(y);
}

// ---------------- split-bf16 mma.sync GEMM ---------------------------------
// 64B rows + XOR swizzle (seg' = c ^ ((r>>1)&3)) -> conflict-free ldsm & stores,
// 3 cp.async stages in 96KB -> still 2 CTAs/SM, ONE __syncthreads per chunk,
// A-fragment register double-buffering.
#define TM 128
#define TN 128
#define KC 32
#define ROWB 64                      // bytes per row (no padding; swizzled)
#define OPB (128 * ROWB)             // 8192 per operand tile
#define STB (4 * OPB)                // 32768 per stage
#define NSTG 3
#define SMEM_BYTES (NSTG * STB)      // 98304

template <int EPI>
__global__ __launch_bounds__(256, 2) void gemm_mma(
    const bf16* __restrict__ Ahi, const bf16* __restrict__ Alo,
    const bf16* __restrict__ Bhi, const bf16* __restrict__ Blo,
    float* __restrict__ C, bf16* __restrict__ Chi, bf16* __restrict__ Clo,
    const float* __restrict__ bias, int K, int ldc)
{
    extern __shared__ char smem[];
    const uint32_t sb = smem_u32(smem);
    const int tid = threadIdx.x, lane = tid & 31, wid = tid >> 5;
    const int wm = wid >> 2, wn = wid & 3;
    const int bn = blockIdx.x * TN, bm = blockIdx.y * TM;
    const int lr = lane >> 2, lc = lane & 3;

    // ldmatrix lane offsets (swizzled), constant per lane per k16
    const int j  = lane >> 3;
    const int rr = ((j & 1) << 3) + (lane & 7);
    const int xr = (rr >> 1) & 3;
    const int cj = j >> 1;
    uint32_t loff[2];
    loff[0] = (uint32_t)(rr * ROWB + (((0 + cj) ^ xr) << 4));
    loff[1] = (uint32_t)(rr * ROWB + (((2 + cj) ^ xr) << 4));

    float acc[4][4][4];
    #pragma unroll
    for (int i = 0; i < 4; i++)
        #pragma unroll
        for (int jj = 0; jj < 4; jj++)
            #pragma unroll
            for (int e = 0; e < 4; e++) acc[i][jj][e] = 0.f;

    const int nc = K / KC;

    auto load_stage = [&](int c) {
        const int buf = c % NSTG;
        const bf16* gs[4] = {
            Ahi + (size_t)bm * K + c * KC,
            Alo + (size_t)bm * K + c * KC,
            Bhi + (size_t)bn * K + c * KC,
            Blo + (size_t)bn * K + c * KC };
        #pragma unroll
        for (int op = 0; op < 4; op++) {
            #pragma unroll
            for (int l = 0; l < 2; l++) {
                const int idx = tid + l * 256;
                const int r = idx & 127, c8 = idx >> 7;
                const uint32_t dst = sb + buf * STB + op * OPB +
                    (uint32_t)(r * ROWB + ((c8 ^ ((r >> 1) & 3)) << 4));
                cp16(dst, gs[op] + (size_t)r * K + c8 * 8);
            }
        }
        asm volatile("cp.async.commit_group;" ::: "memory");
    };

    load_stage(0);
    if (nc > 1) load_stage(1);

    for (int c = 0; c < nc; c++) {
        if (c < nc - 1) {
            asm volatile("cp.async.wait_group 1;" ::: "memory");
        } else {
            asm volatile("cp.async.wait_group 0;" ::: "memory");
        }
        __syncthreads();
        if (c + 2 < nc) load_stage(c + 2);   // writes buf (c-1)%3: safe post-sync

        const uint32_t st = sb + (c % NSTG) * STB;
        const uint32_t aB = st + (uint32_t)(wm * 64 * ROWB);          // A tile base
        const uint32_t bB = st + 2 * OPB + (uint32_t)(wn * 32 * ROWB); // Bhi tile base

        #pragma unroll
        for (int k16 = 0; k16 < 2; k16++) {
            const uint32_t lo = loff[k16];
            uint32_t bh[4][2], bl[4][2];
            #pragma unroll
            for (int ntp = 0; ntp < 2; ntp++) {
                const uint32_t nb = bB + (uint32_t)(ntp * 16 * ROWB) + lo;
                ldsm4(bh[2*ntp][0], bh[2*ntp+1][0], bh[2*ntp][1], bh[2*ntp+1][1], nb);
                ldsm4(bl[2*ntp][0], bl[2*ntp+1][0], bl[2*ntp][1], bl[2*ntp+1][1], nb + OPB);
            }
            // A-fragment register double buffer
            uint32_t ah[2][4], al[2][4];
            ldsm4(ah[0][0], ah[0][1], ah[0][2], ah[0][3], aB + lo);
            ldsm4(al[0][0], al[0][1], al[0][2], al[0][3], aB + OPB + lo);
            #pragma unroll
            for (int mt = 0; mt < 4; mt++) {
                const int cur = mt & 1, nxt = cur ^ 1;
                if (mt < 3) {
                    const uint32_t ab = aB + (uint32_t)((mt + 1) * 16 * ROWB) + lo;
                    ldsm4(ah[nxt][0], ah[nxt][1], ah[nxt][2], ah[nxt][3], ab);
                    ldsm4(al[nxt][0], al[nxt][1], al[nxt][2], al[nxt][3], ab + OPB);
                }
                #pragma unroll
                for (int nt = 0; nt < 4; nt++) {
                    mma_bf16(acc[mt][nt], ah[cur], bh[nt]);
                    mma_bf16(acc[mt][nt], ah[cur], bl[nt]);
                    mma_bf16(acc[mt][nt], al[cur], bh[nt]);
                }
            }
        }
    }

    // -------- epilogue --------
    #pragma unroll
    for (int mt = 0; mt < 4; mt++) {
        #pragma unroll
        for (int nt = 0; nt < 4; nt++) {
            const int row = bm + wm * 64 + mt * 16 + lr;
            const int col = bn + wn * 32 + nt * 8 + lc * 2;
            float v0 = acc[mt][nt][0], v1 = acc[mt][nt][1];
            float v2 = acc[mt][nt][2], v3 = acc[mt][nt][3];
            if (bias) {
                const float b0 = __ldg(bias + col), b1 = __ldg(bias + col + 1);
                v0 += b0; v1 += b1; v2 += b0; v3 += b1;
            }
            if (EPI == 0) {
                *(float2*)(C + (size_t)row * ldc + col)       = make_float2(v0, v1);
                *(float2*)(C + (size_t)(row + 8) * ldc + col) = make_float2(v2, v3);
            } else {
                float vv[4] = {v0, v1, v2, v3};
                uint32_t hp[2], lp[2];
                #pragma unroll
                for (int e = 0; e < 4; e++) {
                    bf16 h = __float2bfloat16(vv[e]);
                    bf16 l = __float2bfloat16(vv[e] - __bfloat162float(h));
                    const uint32_t hb = (uint32_t)__bfloat16_as_ushort(h);
                    const uint32_t lb = (uint32_t)__bfloat16_as_ushort(l);
                    if (e & 1) { hp[e >> 1] |= hb << 16; lp[e >> 1] |= lb << 16; }
                    else       { hp[e >> 1]  = hb;       lp[e >> 1]  = lb; }
                }
                *(uint32_t*)(Chi + (size_t)row * ldc + col)       = hp[0];
                *(uint32_t*)(Chi + (size_t)(row + 8) * ldc + col) = hp[1];
                *(uint32_t*)(Clo + (size_t)row * ldc + col)       = lp[0];
                *(uint32_t*)(Clo + (size_t)(row + 8) * ldc + col) = lp[1];
            }
        }
    }
}

// ---------------- fused conversion kernel (ONE launch) ---------------------
__global__ __launch_bounds__(256) void conv_all(
    const float* __restrict__ x, bf16* __restrict__ xhi, bf16* __restrict__ xlo,
    const float* __restrict__ W1, const float* __restrict__ W2,
    const float* __restrict__ fc1w, const float* __restrict__ fc2w,
    bf16* __restrict__ w1h, bf16* __restrict__ w1l,
    bf16* __restrict__ w2h, bf16* __restrict__ w2l,
    bf16* __restrict__ f1h, bf16* __restrict__ f1l,
    bf16* __restrict__ f2h, bf16* __restrict__ f2l)
{
    __shared__ float tile[32][33];
    const int tid = threadIdx.x;
    int b = blockIdx.x;

    if (b < 4096) {                       // x split: 1048576 float4s
        const int i = b * 256 + tid;
        float4 v = ((const float4*)x)[i];
        float vv[4] = {v.x, v.y, v.z, v.w};
        uint32_t hp[2], lp[2];
        #pragma unroll
        for (int e = 0; e < 4; e++) {
            bf16 h = __float2bfloat16(vv[e]);
            bf16 l = __float2bfloat16(vv[e] - __bfloat162float(h));
            const uint32_t hb = (uint32_t)__bfloat16_as_ushort(h);
            const uint32_t lb = (uint32_t)__bfloat16_as_ushort(l);
            if (e & 1) { hp[e >> 1] |= hb << 16; lp[e >> 1] |= lb << 16; }
            else       { hp[e >> 1]  = hb;       lp[e >> 1]  = lb; }
        }
        ((uint2*)xhi)[i] = make_uint2(hp[0], hp[1]);
        ((uint2*)xlo)[i] = make_uint2(lp[0], lp[1]);
        return;
    }
    b -= 4096;

    const float* B; bf16 *Th, *Tl;
    int K, N, n_off, out_ld, bx, by;
    if (b < 96) {                          // W1: 3 q x (8 n, 4 k)
        const int q = b / 32, r = b % 32;
        B = W1 + (size_t)q * 128 * 256; Th = w1h; Tl = w1l;
        K = 128; N = 256; n_off = q * 256; out_ld = 128;
        bx = r % 8; by = r / 8;
    } else if (b < 96 + 192) {             // W2: 3 q x (8 n, 8 k)
        b -= 96;
        const int q = b / 64, r = b % 64;
        B = W2 + (size_t)q * 256 * 256; Th = w2h; Tl = w2l;
        K = 256; N = 256; n_off = q * 256; out_ld = 256;
        bx = r % 8; by = r / 8;
    } else if (b < 288 + 512) {            // fc1: (64 n, 8 k)
        b -= 288;
        B = fc1w; Th = f1h; Tl = f1l;
        K = 256; N = 2048; n_off = 0; out_ld = 256;
        bx = b % 64; by = b / 64;
    } else {                               // fc2: (8 n, 64 k)
        b -= 800;
        B = fc2w; Th = f2h; Tl = f2l;
        K = 2048; N = 256; n_off = 0; out_ld = 2048;
        bx = b % 8; by = b / 8;
    }

    const int n0 = bx * 32, k0 = by * 32;
    const int tx = tid & 31, ty = tid >> 5;   // 32 x 8
    #pragma unroll
    for (int i = 0; i < 4; i++) {
        const int r = ty + i * 8;
        tile[r][tx] = B[(size_t)(k0 + r) * N + n0 + tx];
    }
    __syncthreads();
    #pragma unroll
    for (int i = 0; i < 4; i++) {
        const int n = ty + i * 8;
        const float v = tile[tx][n];
        bf16 h = __float2bfloat16(v);
        bf16 l = __float2bfloat16(v - __bfloat162float(h));
        const size_t o = (size_t)(n_off + n0 + n) * out_ld + k0 + tx;
        Th[o] = h; Tl[o] = l;
    }
}

// ---------------- attention (f32x2 packed FMA, no-max softmax) -------------
__device__ __forceinline__ void write_split16(const float* o, float inv,
                                              bf16* Hb, bf16* Lb, size_t off)
{
    uint32_t hp[8], lp[8];
    #pragma unroll
    for (int b = 0; b < 16; b++) {
        const float v = o[b] * inv;
        bf16 h = __float2bfloat16(v);
        bf16 l = __float2bfloat16(v - __bfloat162float(h));
        const uint32_t hb = (uint32_t)__bfloat16_as_ushort(h);
        const uint32_t lb = (uint32_t)__bfloat16_as_ushort(l);
        if (b & 1) { hp[b >> 1] |= hb << 16; lp[b >> 1] |= lb << 16; }
        else       { hp[b >> 1]  = hb;       lp[b >> 1]  = lb; }
    }
    *(uint4*)(Hb + off)     = make_uint4(hp[0], hp[1], hp[2], hp[3]);
    *(uint4*)(Hb + off + 8) = make_uint4(hp[4], hp[5], hp[6], hp[7]);
    *(uint4*)(Lb + off)     = make_uint4(lp[0], lp[1], lp[2], lp[3]);
    *(uint4*)(Lb + off + 8) = make_uint4(lp[4], lp[5], lp[6], lp[7]);
}

template <int SEQ>
__device__ __forceinline__ void attn_body(
    const float* __restrict__ base,      // q|k|v row for this thread
    float (*ks)[16], float (*vs)[16],
    float* o, float& l, const int me)
{
    u64 q2[8];
    #pragma unroll
    for (int c = 0; c < 4; c++) {
        ulonglong2 qq = *(const ulonglong2*)(base + c * 4);
        q2[c * 2] = qq.x; q2[c * 2 + 1] = qq.y;
        *(float4*)(&ks[me][c * 4]) = *(const float4*)(base + 256 + c * 4);
        *(float4*)(&vs[me][c * 4]) = *(const float4*)(base + 512 + c * 4);
    }
    __syncthreads();

    u64 o2[8];
    #pragma unroll
    for (int p = 0; p < 8; p++) o2[p] = 0ULL;
    l = 0.f;

    for (int I = 0; I < SEQ; I++) {
        const ulonglong2* kp = (const ulonglong2*)ks[I];
        ulonglong2 ka = kp[0], kb = kp[1], kc = kp[2], kd = kp[3];
        u64 a0 = fma2(q2[0], ka.x, 0ULL);
        u64 a1 = fma2(q2[1], ka.y, 0ULL);
        a0 = fma2(q2[2], kb.x, a0);
        a1 = fma2(q2[3], kb.y, a1);
        a0 = fma2(q2[4], kc.x, a0);
        a1 = fma2(q2[5], kc.y, a1);
        a0 = fma2(q2[6], kd.x, a0);
        a1 = fma2(q2[7], kd.y, a1);
        a0 = add2(a0, a1);
        float s0, s1;
        unpack2(a0, s0, s1);
        const float e = __expf(s0 + s1);
        l += e;
        const u64 e2 = pack2(e, e);
        const ulonglong2* vp = (const ulonglong2*)vs[I];
        ulonglong2 va = vp[0], vb = vp[1], vc = vp[2], vd = vp[3];
        o2[0] = fma2(e2, va.x, o2[0]);
        o2[1] = fma2(e2, va.y, o2[1]);
        o2[2] = fma2(e2, vb.x, o2[2]);
        o2[3] = fma2(e2, vb.y, o2[3]);
        o2[4] = fma2(e2, vc.x, o2[4]);
        o2[5] = fma2(e2, vc.y, o2[5]);
        o2[6] = fma2(e2, vd.x, o2[6]);
        o2[7] = fma2(e2, vd.y, o2[7]);
    }
    #pragma unroll
    for (int p = 0; p < 8; p++) unpack2(o2[p], o[2 * p], o[2 * p + 1]);
}

__global__ __launch_bounds__(128) void temporal_attn(
    const float* __restrict__ y1, bf16* __restrict__ tH, bf16* __restrict__ tL)
{
    const int j = blockIdx.x, a = blockIdx.y, i = threadIdx.x;
    __shared__ float ks[128][16];
    __shared__ float vs[128][16];
    const float* base = y1 + ((size_t)i * 256 + j) * 768 + a * 16;
    float o[16], l;
    attn_body<128>(base, ks, vs, o, l, i);
    write_split16(o, 1.f / l, tH, tL, ((size_t)i * 256 + j) * 256 + a * 16);
}

__global__ __launch_bounds__(256) void point_attn(
    const float* __restrict__ y2, bf16* __restrict__ pH, bf16* __restrict__ pL)
{
    const int i = blockIdx.x, a = blockIdx.y, j = threadIdx.x;
    __shared__ float ks[256][16];
    __shared__ float vs[256][16];
    const float* base = y2 + ((size_t)i * 256 + j) * 768 + a * 16;
    float o[16], l;
    attn_body<256>(base, ks, vs, o, l, j);
    write_split16(o, 1.f / l, pH, pL, ((size_t)i * 256 + j) * 256 + a * 16);
}

// ---------------------------------------------------------------------------
extern "C" void kernel_launch(void* const* d_in, const int* in_sizes, int n_in,
                              void* d_out, int out_size)
{
    const float* x     = (const float*)d_in[0];
    const float* W1    = (const float*)d_in[1];
    const float* W2    = (const float*)d_in[2];
    const float* fc1_w = (const float*)d_in[3];
    const float* fc1_b = (const float*)d_in[4];
    const float* fc2_w = (const float*)d_in[5];
    const float* fc2_b = (const float*)d_in[6];
    float* out = (float*)d_out;

    bf16 *xhi, *xlo, *thi, *tlo, *pahi, *palo, *hhi, *hlo;
    bf16 *w1h, *w1l, *w2h, *w2l, *f1h, *f1l, *f2h, *f2l;
    float *y1, *y2;
    cudaGetSymbolAddress((void**)&xhi, g_xhi);  cudaGetSymbolAddress((void**)&xlo, g_xlo);
    cudaGetSymbolAddress((void**)&y1, g_y1);    cudaGetSymbolAddress((void**)&y2, g_y2);
    cudaGetSymbolAddress((void**)&thi, g_thi);  cudaGetSymbolAddress((void**)&tlo, g_tlo);
    cudaGetSymbolAddress((void**)&pahi, g_pahi); cudaGetSymbolAddress((void**)&palo, g_palo);
    cudaGetSymbolAddress((void**)&hhi, g_hhi);  cudaGetSymbolAddress((void**)&hlo, g_hlo);
    cudaGetSymbolAddress((void**)&w1h, g_w1t_hi); cudaGetSymbolAddress((void**)&w1l, g_w1t_lo);
    cudaGetSymbolAddress((void**)&w2h, g_w2t_hi); cudaGetSymbolAddress((void**)&w2l, g_w2t_lo);
    cudaGetSymbolAddress((void**)&f1h, g_f1t_hi); cudaGetSymbolAddress((void**)&f1l, g_f1t_lo);
    cudaGetSymbolAddress((void**)&f2h, g_f2t_hi); cudaGetSymbolAddress((void**)&f2l, g_f2t_lo);

    cudaFuncSetAttribute(gemm_mma<0>, cudaFuncAttributeMaxDynamicSharedMemorySize, SMEM_BYTES);
    cudaFuncSetAttribute(gemm_mma<1>, cudaFuncAttributeMaxDynamicSharedMemorySize, SMEM_BYTES);

    // 0) all conversions in ONE launch
    conv_all<<<5408, 256>>>(x, xhi, xlo, W1, W2, fc1_w, fc2_w,
                            w1h, w1l, w2h, w2l, f1h, f1l, f2h, f2l);
    // 1) QKV1: y1[32768,768] = x @ W1
    gemm_mma<0><<<dim3(768 / TN, ROWS / TM), 256, SMEM_BYTES>>>(
        xhi, xlo, w1h, w1l, y1, nullptr, nullptr, nullptr, 128, 768);
    // 2) temporal attention -> split t
    temporal_attn<<<dim3(PP, HD), 128>>>(y1, thi, tlo);
    // 3) QKV2
    gemm_mma<0><<<dim3(768 / TN, ROWS / TM), 256, SMEM_BYTES>>>(
        thi, tlo, w2h, w2l, y2, nullptr, nullptr, nullptr, 256, 768);
    // 4) point attention -> split pa
    point_attn<<<dim3(NN, HD), 256>>>(y2, pahi, palo);
    // 5) FC1 (+bias) -> split h      [launch index 5: ncu capture target]
    gemm_mma<1><<<dim3(HIDDEN / TN, ROWS / TM), 256, SMEM_BYTES>>>(
        pahi, palo, f1h, f1l, nullptr, hhi, hlo, fc1_b, 256, HIDDEN);
    // 6) FC2 (+bias) -> out
    gemm_mma<0><<<dim3(256 / TN, ROWS / TM), 256, SMEM_BYTES>>>(
        hhi, hlo, f2h, f2l, out, nullptr, nullptr, fc2_b, 2048, 256);
}

// round 10
// speedup vs baseline: 1.3222x; 1.3222x over previous
#include <cuda_runtime.h>
#include <cuda_bf16.h>
#include <cstdint>

typedef __nv_bfloat16 bf16;
typedef unsigned long long u64;

#define NN 128
#define PP 256
#define DD 128
#define HD 16
#define ROWS (NN*PP)      // 32768
#define HIDDEN 2048

// ---------------- scratch (device globals; no cudaMalloc allowed) ----------
__device__ bf16  g_xhi[(size_t)ROWS * DD],    g_xlo[(size_t)ROWS * DD];
__device__ float g_y1 [(size_t)ROWS * 768];
__device__ bf16  g_thi[(size_t)ROWS * 256],   g_tlo[(size_t)ROWS * 256];
__device__ float g_y2 [(size_t)ROWS * 768];
__device__ bf16  g_pahi[(size_t)ROWS * 256],  g_palo[(size_t)ROWS * 256];
__device__ bf16  g_hhi[(size_t)ROWS * HIDDEN], g_hlo[(size_t)ROWS * HIDDEN];
// transposed split weights: Bt[n][k]
__device__ bf16  g_w1t_hi[768 * 128],   g_w1t_lo[768 * 128];
__device__ bf16  g_w2t_hi[768 * 256],   g_w2t_lo[768 * 256];
__device__ bf16  g_f1t_hi[2048 * 256],  g_f1t_lo[2048 * 256];
__device__ bf16  g_f2t_hi[256 * 2048],  g_f2t_lo[256 * 2048];

// ---------------- helpers ---------------------------------------------------
__device__ __forceinline__ uint32_t smem_u32(const void* p) {
    uint32_t a;
    asm("{ .reg .u64 t; cvta.to.shared.u64 t, %1; cvt.u32.u64 %0, t; }"
        : "=r"(a) : "l"(p));
    return a;
}
__device__ __forceinline__ void cp16(uint32_t dst, const void* src) {
    asm volatile("cp.async.cg.shared.global [%0], [%1], 16;"
                 :: "r"(dst), "l"(src) : "memory");
}
__device__ __forceinline__ void mma_bf16(float* d, const uint32_t* a, const uint32_t* b) {
    asm volatile(
        "mma.sync.aligned.m16n8k16.row.col.f32.bf16.bf16.f32 "
        "{%0,%1,%2,%3}, {%4,%5,%6,%7}, {%8,%9}, {%0,%1,%2,%3};"
        : "+f"(d[0]), "+f"(d[1]), "+f"(d[2]), "+f"(d[3])
        : "r"(a[0]), "r"(a[1]), "r"(a[2]), "r"(a[3]), "r"(b[0]), "r"(b[1]));
}
__device__ __forceinline__ void ldsm4(uint32_t& r0, uint32_t& r1, uint32_t& r2,
                                      uint32_t& r3, uint32_t addr) {
    asm volatile("ldmatrix.sync.aligned.m8n8.x4.shared.b16 {%0,%1,%2,%3}, [%4];"
                 : "=r"(r0), "=r"(r1), "=r"(r2), "=r"(r3) : "r"(addr));
}
// packed f32x2 (Blackwell FFMA2 path)
__device__ __forceinline__ u64 fma2(u64 a, u64 b, u64 c) {
    u64 d; asm("fma.rn.f32x2 %0, %1, %2, %3;" : "=l"(d) : "l"(a), "l"(b), "l"(c));
    return d;
}
__device__ __forceinline__ u64 add2(u64 a, u64 b) {
    u64 d; asm("add.rn.f32x2 %0, %1, %2;" : "=l"(d) : "l"(a), "l"(b));
    return d;
}
__device__ __forceinline__ u64 pack2(float a, float b) {
    u64 d; asm("mov.b64 %0, {%1, %2};" : "=l"(d)
               : "r"(__float_as_uint(a)), "r"(__float_as_uint(b)));
    return d;
}
__device__ __forceinline__ void unpack2(u64 v, float& a, float& b) {
    uint32_t x, y;
    asm("mov.b64 {%0, %1}, %2;" : "=r"(x), "=r"(y) : "l"(v));
    a = __uint_as_float(x); b = __uint_as_float(y);
}

// ---------------- split-bf16 mma.sync GEMM ---------------------------------
// 64B rows + XOR swizzle (seg' = c ^ ((r>>1)&3)), COALESCED loader
// (r = idx>>2, c8 = idx&3: 4 threads cover one contiguous 64B row segment),
// 3 cp.async stages in 96KB -> 2 CTAs/SM, one __syncthreads per chunk,
// A-fragment register double-buffering.
#define TM 128
#define TN 128
#define KC 32
#define ROWB 64                      // bytes per row (no padding; swizzled)
#define OPB (128 * ROWB)             // 8192 per operand tile
#define STB (4 * OPB)                // 32768 per stage
#define NSTG 3
#define SMEM_BYTES (NSTG * STB)      // 98304

template <int EPI>
__global__ __launch_bounds__(256, 2) void gemm_mma(
    const bf16* __restrict__ Ahi, const bf16* __restrict__ Alo,
    const bf16* __restrict__ Bhi, const bf16* __restrict__ Blo,
    float* __restrict__ C, bf16* __restrict__ Chi, bf16* __restrict__ Clo,
    const float* __restrict__ bias, int K, int ldc)
{
    extern __shared__ char smem[];
    const uint32_t sb = smem_u32(smem);
    const int tid = threadIdx.x, lane = tid & 31, wid = tid >> 5;
    const int wm = wid >> 2, wn = wid & 3;
    const int bn = blockIdx.x * TN, bm = blockIdx.y * TM;
    const int lr = lane >> 2, lc = lane & 3;

    // ldmatrix lane offsets (swizzled), constant per lane per k16
    const int j  = lane >> 3;
    const int rr = ((j & 1) << 3) + (lane & 7);
    const int xr = (rr >> 1) & 3;
    const int cj = j >> 1;
    uint32_t loff[2];
    loff[0] = (uint32_t)(rr * ROWB + (((0 + cj) ^ xr) << 4));
    loff[1] = (uint32_t)(rr * ROWB + (((2 + cj) ^ xr) << 4));

    float acc[4][4][4];
    #pragma unroll
    for (int i = 0; i < 4; i++)
        #pragma unroll
        for (int jj = 0; jj < 4; jj++)
            #pragma unroll
            for (int e = 0; e < 4; e++) acc[i][jj][e] = 0.f;

    const int nc = K / KC;

    auto load_stage = [&](int c) {
        const int buf = c % NSTG;
        const bf16* gs[4] = {
            Ahi + (size_t)bm * K + c * KC,
            Alo + (size_t)bm * K + c * KC,
            Bhi + (size_t)bn * K + c * KC,
            Blo + (size_t)bn * K + c * KC };
        #pragma unroll
        for (int op = 0; op < 4; op++) {
            #pragma unroll
            for (int l = 0; l < 2; l++) {
                const int idx = tid + l * 256;
                const int r = idx >> 2, c8 = idx & 3;       // coalesced 64B/4thr
                const uint32_t dst = sb + buf * STB + op * OPB +
                    (uint32_t)(r * ROWB + ((c8 ^ ((r >> 1) & 3)) << 4));
                cp16(dst, gs[op] + (size_t)r * K + c8 * 8);
            }
        }
        asm volatile("cp.async.commit_group;" ::: "memory");
    };

    load_stage(0);
    if (nc > 1) load_stage(1);

    for (int c = 0; c < nc; c++) {
        if (c < nc - 1) {
            asm volatile("cp.async.wait_group 1;" ::: "memory");
        } else {
            asm volatile("cp.async.wait_group 0;" ::: "memory");
        }
        __syncthreads();
        if (c + 2 < nc) load_stage(c + 2);   // writes buf (c-1)%3: safe post-sync

        const uint32_t st = sb + (c % NSTG) * STB;
        const uint32_t aB = st + (uint32_t)(wm * 64 * ROWB);           // A tile base
        const uint32_t bB = st + 2 * OPB + (uint32_t)(wn * 32 * ROWB); // Bhi tile base

        #pragma unroll
        for (int k16 = 0; k16 < 2; k16++) {
            const uint32_t lo = loff[k16];
            uint32_t bh[4][2], bl[4][2];
            #pragma unroll
            for (int ntp = 0; ntp < 2; ntp++) {
                const uint32_t nb = bB + (uint32_t)(ntp * 16 * ROWB) + lo;
                ldsm4(bh[2*ntp][0], bh[2*ntp+1][0], bh[2*ntp][1], bh[2*ntp+1][1], nb);
                ldsm4(bl[2*ntp][0], bl[2*ntp+1][0], bl[2*ntp][1], bl[2*ntp+1][1], nb + OPB);
            }
            // A-fragment register double buffer
            uint32_t ah[2][4], al[2][4];
            ldsm4(ah[0][0], ah[0][1], ah[0][2], ah[0][3], aB + lo);
            ldsm4(al[0][0], al[0][1], al[0][2], al[0][3], aB + OPB + lo);
            #pragma unroll
            for (int mt = 0; mt < 4; mt++) {
                const int cur = mt & 1, nxt = cur ^ 1;
                if (mt < 3) {
                    const uint32_t ab = aB + (uint32_t)((mt + 1) * 16 * ROWB) + lo;
                    ldsm4(ah[nxt][0], ah[nxt][1], ah[nxt][2], ah[nxt][3], ab);
                    ldsm4(al[nxt][0], al[nxt][1], al[nxt][2], al[nxt][3], ab + OPB);
                }
                #pragma unroll
                for (int nt = 0; nt < 4; nt++) {
                    mma_bf16(acc[mt][nt], ah[cur], bh[nt]);
                    mma_bf16(acc[mt][nt], ah[cur], bl[nt]);
                    mma_bf16(acc[mt][nt], al[cur], bh[nt]);
                }
            }
        }
    }

    // -------- epilogue --------
    #pragma unroll
    for (int mt = 0; mt < 4; mt++) {
        #pragma unroll
        for (int nt = 0; nt < 4; nt++) {
            const int row = bm + wm * 64 + mt * 16 + lr;
            const int col = bn + wn * 32 + nt * 8 + lc * 2;
            float v0 = acc[mt][nt][0], v1 = acc[mt][nt][1];
            float v2 = acc[mt][nt][2], v3 = acc[mt][nt][3];
            if (bias) {
                const float b0 = __ldg(bias + col), b1 = __ldg(bias + col + 1);
                v0 += b0; v1 += b1; v2 += b0; v3 += b1;
            }
            if (EPI == 0) {
                *(float2*)(C + (size_t)row * ldc + col)       = make_float2(v0, v1);
                *(float2*)(C + (size_t)(row + 8) * ldc + col) = make_float2(v2, v3);
            } else {
                float vv[4] = {v0, v1, v2, v3};
                uint32_t hp[2], lp[2];
                #pragma unroll
                for (int e = 0; e < 4; e++) {
                    bf16 h = __float2bfloat16(vv[e]);
                    bf16 l = __float2bfloat16(vv[e] - __bfloat162float(h));
                    const uint32_t hb = (uint32_t)__bfloat16_as_ushort(h);
                    const uint32_t lb = (uint32_t)__bfloat16_as_ushort(l);
                    if (e & 1) { hp[e >> 1] |= hb << 16; lp[e >> 1] |= lb << 16; }
                    else       { hp[e >> 1]  = hb;       lp[e >> 1]  = lb; }
                }
                *(uint32_t*)(Chi + (size_t)row * ldc + col)       = hp[0];
                *(uint32_t*)(Chi + (size_t)(row + 8) * ldc + col) = hp[1];
                *(uint32_t*)(Clo + (size_t)row * ldc + col)       = lp[0];
                *(uint32_t*)(Clo + (size_t)(row + 8) * ldc + col) = lp[1];
            }
        }
    }
}

// ---------------- fused conversion kernel (ONE launch) ---------------------
__global__ __launch_bounds__(256) void conv_all(
    const float* __restrict__ x, bf16* __restrict__ xhi, bf16* __restrict__ xlo,
    const float* __restrict__ W1, const float* __restrict__ W2,
    const float* __restrict__ fc1w, const float* __restrict__ fc2w,
    bf16* __restrict__ w1h, bf16* __restrict__ w1l,
    bf16* __restrict__ w2h, bf16* __restrict__ w2l,
    bf16* __restrict__ f1h, bf16* __restrict__ f1l,
    bf16* __restrict__ f2h, bf16* __restrict__ f2l)
{
    __shared__ float tile[32][33];
    const int tid = threadIdx.x;
    int b = blockIdx.x;

    if (b < 4096) {                       // x split: 1048576 float4s
        const int i = b * 256 + tid;
        float4 v = ((const float4*)x)[i];
        float vv[4] = {v.x, v.y, v.z, v.w};
        uint32_t hp[2], lp[2];
        #pragma unroll
        for (int e = 0; e < 4; e++) {
            bf16 h = __float2bfloat16(vv[e]);
            bf16 l = __float2bfloat16(vv[e] - __bfloat162float(h));
            const uint32_t hb = (uint32_t)__bfloat16_as_ushort(h);
            const uint32_t lb = (uint32_t)__bfloat16_as_ushort(l);
            if (e & 1) { hp[e >> 1] |= hb << 16; lp[e >> 1] |= lb << 16; }
            else       { hp[e >> 1]  = hb;       lp[e >> 1]  = lb; }
        }
        ((uint2*)xhi)[i] = make_uint2(hp[0], hp[1]);
        ((uint2*)xlo)[i] = make_uint2(lp[0], lp[1]);
        return;
    }
    b -= 4096;

    const float* B; bf16 *Th, *Tl;
    int K, N, n_off, out_ld, bx, by;
    if (b < 96) {                          // W1: 3 q x (8 n, 4 k)
        const int q = b / 32, r = b % 32;
        B = W1 + (size_t)q * 128 * 256; Th = w1h; Tl = w1l;
        K = 128; N = 256; n_off = q * 256; out_ld = 128;
        bx = r % 8; by = r / 8;
    } else if (b < 96 + 192) {             // W2: 3 q x (8 n, 8 k)
        b -= 96;
        const int q = b / 64, r = b % 64;
        B = W2 + (size_t)q * 256 * 256; Th = w2h; Tl = w2l;
        K = 256; N = 256; n_off = q * 256; out_ld = 256;
        bx = r % 8; by = r / 8;
    } else if (b < 288 + 512) {            // fc1: (64 n, 8 k)
        b -= 288;
        B = fc1w; Th = f1h; Tl = f1l;
        K = 256; N = 2048; n_off = 0; out_ld = 256;
        bx = b % 64; by = b / 64;
    } else {                               // fc2: (8 n, 64 k)
        b -= 800;
        B = fc2w; Th = f2h; Tl = f2l;
        K = 2048; N = 256; n_off = 0; out_ld = 2048;
        bx = b % 8; by = b / 8;
    }

    const int n0 = bx * 32, k0 = by * 32;
    const int tx = tid & 31, ty = tid >> 5;   // 32 x 8
    #pragma unroll
    for (int i = 0; i < 4; i++) {
        const int r = ty + i * 8;
        tile[r][tx] = B[(size_t)(k0 + r) * N + n0 + tx];
    }
    __syncthreads();
    #pragma unroll
    for (int i = 0; i < 4; i++) {
        const int n = ty + i * 8;
        const float v = tile[tx][n];
        bf16 h = __float2bfloat16(v);
        bf16 l = __float2bfloat16(v - __bfloat162float(h));
        const size_t o = (size_t)(n_off + n0 + n) * out_ld + k0 + tx;
        Th[o] = h; Tl[o] = l;
    }
}

// ---------------- attention (f32x2 packed FMA, no-max softmax) -------------
__device__ __forceinline__ void write_split16(const float* o, float inv,
                                              bf16* Hb, bf16* Lb, size_t off)
{
    uint32_t hp[8], lp[8];
    #pragma unroll
    for (int b = 0; b < 16; b++) {
        const float v = o[b] * inv;
        bf16 h = __float2bfloat16(v);
        bf16 l = __float2bfloat16(v - __bfloat162float(h));
        const uint32_t hb = (uint32_t)__bfloat16_as_ushort(h);
        const uint32_t lb = (uint32_t)__bfloat16_as_ushort(l);
        if (b & 1) { hp[b >> 1] |= hb << 16; lp[b >> 1] |= lb << 16; }
        else       { hp[b >> 1]  = hb;       lp[b >> 1]  = lb; }
    }
    *(uint4*)(Hb + off)     = make_uint4(hp[0], hp[1], hp[2], hp[3]);
    *(uint4*)(Hb + off + 8) = make_uint4(hp[4], hp[5], hp[6], hp[7]);
    *(uint4*)(Lb + off)     = make_uint4(lp[0], lp[1], lp[2], lp[3]);
    *(uint4*)(Lb + off + 8) = make_uint4(lp[4], lp[5], lp[6], lp[7]);
}

template <int SEQ>
__device__ __forceinline__ void attn_body(
    const float* __restrict__ base,      // q|k|v row for this thread
    float (*ks)[16], float (*vs)[16],
    float* o, float& l, const int me)
{
    u64 q2[8];
    #pragma unroll
    for (int c = 0; c < 4; c++) {
        ulonglong2 qq = *(const ulonglong2*)(base + c * 4);
        q2[c * 2] = qq.x; q2[c * 2 + 1] = qq.y;
        *(float4*)(&ks[me][c * 4]) = *(const float4*)(base + 256 + c * 4);
        *(float4*)(&vs[me][c * 4]) = *(const float4*)(base + 512 + c * 4);
    }
    __syncthreads();

    u64 o2[8];
    #pragma unroll
    for (int p = 0; p < 8; p++) o2[p] = 0ULL;
    l = 0.f;

    for (int I = 0; I < SEQ; I++) {
        const ulonglong2* kp = (const ulonglong2*)ks[I];
        ulonglong2 ka = kp[0], kb = kp[1], kc = kp[2], kd = kp[3];
        u64 a0 = fma2(q2[0], ka.x, 0ULL);
        u64 a1 = fma2(q2[1], ka.y, 0ULL);
        a0 = fma2(q2[2], kb.x, a0);
        a1 = fma2(q2[3], kb.y, a1);
        a0 = fma2(q2[4], kc.x, a0);
        a1 = fma2(q2[5], kc.y, a1);
        a0 = fma2(q2[6], kd.x, a0);
        a1 = fma2(q2[7], kd.y, a1);
        a0 = add2(a0, a1);
        float s0, s1;
        unpack2(a0, s0, s1);
        const float e = __expf(s0 + s1);
        l += e;
        const u64 e2 = pack2(e, e);
        const ulonglong2* vp = (const ulonglong2*)vs[I];
        ulonglong2 va = vp[0], vb = vp[1], vc = vp[2], vd = vp[3];
        o2[0] = fma2(e2, va.x, o2[0]);
        o2[1] = fma2(e2, va.y, o2[1]);
        o2[2] = fma2(e2, vb.x, o2[2]);
        o2[3] = fma2(e2, vb.y, o2[3]);
        o2[4] = fma2(e2, vc.x, o2[4]);
        o2[5] = fma2(e2, vc.y, o2[5]);
        o2[6] = fma2(e2, vd.x, o2[6]);
        o2[7] = fma2(e2, vd.y, o2[7]);
    }
    #pragma unroll
    for (int p = 0; p < 8; p++) unpack2(o2[p], o[2 * p], o[2 * p + 1]);
}

__global__ __launch_bounds__(128) void temporal_attn(
    const float* __restrict__ y1, bf16* __restrict__ tH, bf16* __restrict__ tL)
{
    const int j = blockIdx.x, a = blockIdx.y, i = threadIdx.x;
    __shared__ float ks[128][16];
    __shared__ float vs[128][16];
    const float* base = y1 + ((size_t)i * 256 + j) * 768 + a * 16;
    float o[16], l;
    attn_body<128>(base, ks, vs, o, l, i);
    write_split16(o, 1.f / l, tH, tL, ((size_t)i * 256 + j) * 256 + a * 16);
}

__global__ __launch_bounds__(256) void point_attn(
    const float* __restrict__ y2, bf16* __restrict__ pH, bf16* __restrict__ pL)
{
    const int i = blockIdx.x, a = blockIdx.y, j = threadIdx.x;
    __shared__ float ks[256][16];
    __shared__ float vs[256][16];
    const float* base = y2 + ((size_t)i * 256 + j) * 768 + a * 16;
    float o[16], l;
    attn_body<256>(base, ks, vs, o, l, j);
    write_split16(o, 1.f / l, pH, pL, ((size_t)i * 256 + j) * 256 + a * 16);
}

// ---------------------------------------------------------------------------
extern "C" void kernel_launch(void* const* d_in, const int* in_sizes, int n_in,
                              void* d_out, int out_size)
{
    const float* x     = (const float*)d_in[0];
    const float* W1    = (const float*)d_in[1];
    const float* W2    = (const float*)d_in[2];
    const float* fc1_w = (const float*)d_in[3];
    const float* fc1_b = (const float*)d_in[4];
    const float* fc2_w = (const float*)d_in[5];
    const float* fc2_b = (const float*)d_in[6];
    float* out = (float*)d_out;

    bf16 *xhi, *xlo, *thi, *tlo, *pahi, *palo, *hhi, *hlo;
    bf16 *w1h, *w1l, *w2h, *w2l, *f1h, *f1l, *f2h, *f2l;
    float *y1, *y2;
    cudaGetSymbolAddress((void**)&xhi, g_xhi);  cudaGetSymbolAddress((void**)&xlo, g_xlo);
    cudaGetSymbolAddress((void**)&y1, g_y1);    cudaGetSymbolAddress((void**)&y2, g_y2);
    cudaGetSymbolAddress((void**)&thi, g_thi);  cudaGetSymbolAddress((void**)&tlo, g_tlo);
    cudaGetSymbolAddress((void**)&pahi, g_pahi); cudaGetSymbolAddress((void**)&palo, g_palo);
    cudaGetSymbolAddress((void**)&hhi, g_hhi);  cudaGetSymbolAddress((void**)&hlo, g_hlo);
    cudaGetSymbolAddress((void**)&w1h, g_w1t_hi); cudaGetSymbolAddress((void**)&w1l, g_w1t_lo);
    cudaGetSymbolAddress((void**)&w2h, g_w2t_hi); cudaGetSymbolAddress((void**)&w2l, g_w2t_lo);
    cudaGetSymbolAddress((void**)&f1h, g_f1t_hi); cudaGetSymbolAddress((void**)&f1l, g_f1t_lo);
    cudaGetSymbolAddress((void**)&f2h, g_f2t_hi); cudaGetSymbolAddress((void**)&f2l, g_f2t_lo);

    cudaFuncSetAttribute(gemm_mma<0>, cudaFuncAttributeMaxDynamicSharedMemorySize, SMEM_BYTES);
    cudaFuncSetAttribute(gemm_mma<1>, cudaFuncAttributeMaxDynamicSharedMemorySize, SMEM_BYTES);

    // 0) all conversions in ONE launch
    conv_all<<<5408, 256>>>(x, xhi, xlo, W1, W2, fc1_w, fc2_w,
                            w1h, w1l, w2h, w2l, f1h, f1l, f2h, f2l);
    // 1) QKV1: y1[32768,768] = x @ W1
    gemm_mma<0><<<dim3(768 / TN, ROWS / TM), 256, SMEM_BYTES>>>(
        xhi, xlo, w1h, w1l, y1, nullptr, nullptr, nullptr, 128, 768);
    // 2) temporal attention -> split t
    temporal_attn<<<dim3(PP, HD), 128>>>(y1, thi, tlo);
    // 3) QKV2
    gemm_mma<0><<<dim3(768 / TN, ROWS / TM), 256, SMEM_BYTES>>>(
        thi, tlo, w2h, w2l, y2, nullptr, nullptr, nullptr, 256, 768);
    // 4) point attention -> split pa
    point_attn<<<dim3(NN, HD), 256>>>(y2, pahi, palo);
    // 5) FC1 (+bias) -> split h      [launch index 5: ncu capture target]
    gemm_mma<1><<<dim3(HIDDEN / TN, ROWS / TM), 256, SMEM_BYTES>>>(
        pahi, palo, f1h, f1l, nullptr, hhi, hlo, fc1_b, 256, HIDDEN);
    // 6) FC2 (+bias) -> out
    gemm_mma<0><<<dim3(256 / TN, ROWS / TM), 256, SMEM_BYTES>>>(
        hhi, hlo, f2h, f2l, out, nullptr, nullptr, fc2_b, 2048, 256);
}

// round 11
// speedup vs baseline: 2.4234x; 1.8329x over previous
#include <cuda_runtime.h>
#include <cuda_bf16.h>
#include <cstdint>

typedef __nv_bfloat16 bf16;
typedef unsigned long long u64;

#define NN 128
#define PP 256
#define DD 128
#define HD 16
#define ROWS (NN*PP)      // 32768
#define HIDDEN 2048

// ---------------- scratch (device globals; no cudaMalloc allowed) ----------
__device__ bf16  g_xhi[(size_t)ROWS * DD],    g_xlo[(size_t)ROWS * DD];
__device__ float g_y1 [(size_t)ROWS * 768];
__device__ bf16  g_thi[(size_t)ROWS * 256],   g_tlo[(size_t)ROWS * 256];
__device__ float g_y2 [(size_t)ROWS * 768];
__device__ bf16  g_pahi[(size_t)ROWS * 256],  g_palo[(size_t)ROWS * 256];
// transposed split weights: Bt[n][k]
__device__ bf16  g_w1t_hi[768 * 128],   g_w1t_lo[768 * 128];
__device__ bf16  g_w2t_hi[768 * 256],   g_w2t_lo[768 * 256];
__device__ bf16  g_f2t_hi[256 * 2048],  g_f2t_lo[256 * 2048];   // fc2_w^T split
__device__ bf16  g_f1a_hi[256 * 2048],  g_f1a_lo[256 * 2048];   // fc1_w row-major split
// fused FC weight: W12T = fc2_w^T @ fc1_w^T (split-K partials, then split)
__device__ float g_w12p[8 * 256 * 256];
__device__ bf16  g_w12h[256 * 256],     g_w12l[256 * 256];
__device__ float g_b12[256];

// ---------------- helpers ---------------------------------------------------
__device__ __forceinline__ uint32_t smem_u32(const void* p) {
    uint32_t a;
    asm("{ .reg .u64 t; cvta.to.shared.u64 t, %1; cvt.u32.u64 %0, t; }"
        : "=r"(a) : "l"(p));
    return a;
}
__device__ __forceinline__ void cp16(uint32_t dst, const void* src) {
    asm volatile("cp.async.cg.shared.global [%0], [%1], 16;"
                 :: "r"(dst), "l"(src) : "memory");
}
__device__ __forceinline__ void mma_bf16(float* d, const uint32_t* a, const uint32_t* b) {
    asm volatile(
        "mma.sync.aligned.m16n8k16.row.col.f32.bf16.bf16.f32 "
        "{%0,%1,%2,%3}, {%4,%5,%6,%7}, {%8,%9}, {%0,%1,%2,%3};"
        : "+f"(d[0]), "+f"(d[1]), "+f"(d[2]), "+f"(d[3])
        : "r"(a[0]), "r"(a[1]), "r"(a[2]), "r"(a[3]), "r"(b[0]), "r"(b[1]));
}
__device__ __forceinline__ void ldsm4(uint32_t& r0, uint32_t& r1, uint32_t& r2,
                                      uint32_t& r3, uint32_t addr) {
    asm volatile("ldmatrix.sync.aligned.m8n8.x4.shared.b16 {%0,%1,%2,%3}, [%4];"
                 : "=r"(r0), "=r"(r1), "=r"(r2), "=r"(r3) : "r"(addr));
}
// packed f32x2 (Blackwell FFMA2 path)
__device__ __forceinline__ u64 fma2(u64 a, u64 b, u64 c) {
    u64 d; asm("fma.rn.f32x2 %0, %1, %2, %3;" : "=l"(d) : "l"(a), "l"(b), "l"(c));
    return d;
}
__device__ __forceinline__ u64 add2(u64 a, u64 b) {
    u64 d; asm("add.rn.f32x2 %0, %1, %2;" : "=l"(d) : "l"(a), "l"(b));
    return d;
}
__device__ __forceinline__ u64 pack2(float a, float b) {
    u64 d; asm("mov.b64 %0, {%1, %2};" : "=l"(d)
               : "r"(__float_as_uint(a)), "r"(__float_as_uint(b)));
    return d;
}
__device__ __forceinline__ void unpack2(u64 v, float& a, float& b) {
    uint32_t x, y;
    asm("mov.b64 {%0, %1}, %2;" : "=r"(x), "=r"(y) : "l"(v));
    a = __uint_as_float(x); b = __uint_as_float(y);
}
__device__ __forceinline__ void split1(float v, uint32_t& hb, uint32_t& lb) {
    bf16 h = __float2bfloat16(v);
    bf16 l = __float2bfloat16(v - __bfloat162float(h));
    hb = (uint32_t)__bfloat16_as_ushort(h);
    lb = (uint32_t)__bfloat16_as_ushort(l);
}

// ---------------- split-bf16 mma.sync GEMM ---------------------------------
// 64B rows + XOR swizzle, coalesced loader, 3 cp.async stages (96KB,
// 2 CTAs/SM), one __syncthreads per chunk, A-fragment double buffering.
// EPI=0: fp32 out (+bias). EPI=1: split-bf16 out. EPI=2: fp32 split-K
// partial (C + blockIdx.z*65536, K-slice offset blockIdx.z*K).
#define TM 128
#define TN 128
#define KC 32
#define ROWB 64
#define OPB (128 * ROWB)
#define STB (4 * OPB)
#define NSTG 3
#define SMEM_BYTES (NSTG * STB)      // 98304

template <int EPI>
__global__ __launch_bounds__(256, 2) void gemm_mma(
    const bf16* __restrict__ Ahi, const bf16* __restrict__ Alo,
    const bf16* __restrict__ Bhi, const bf16* __restrict__ Blo,
    float* __restrict__ C, bf16* __restrict__ Chi, bf16* __restrict__ Clo,
    const float* __restrict__ bias, int K, int ldc, int lda)
{
    extern __shared__ char smem[];
    const uint32_t sb = smem_u32(smem);
    const int tid = threadIdx.x, lane = tid & 31, wid = tid >> 5;
    const int wm = wid >> 2, wn = wid & 3;
    const int bn = blockIdx.x * TN, bm = blockIdx.y * TM;
    const int lr = lane >> 2, lc = lane & 3;
    const int koff = (EPI == 2) ? (int)blockIdx.z * K : 0;

    const int j  = lane >> 3;
    const int rr = ((j & 1) << 3) + (lane & 7);
    const int xr = (rr >> 1) & 3;
    const int cj = j >> 1;
    uint32_t loff[2];
    loff[0] = (uint32_t)(rr * ROWB + (((0 + cj) ^ xr) << 4));
    loff[1] = (uint32_t)(rr * ROWB + (((2 + cj) ^ xr) << 4));

    float acc[4][4][4];
    #pragma unroll
    for (int i = 0; i < 4; i++)
        #pragma unroll
        for (int jj = 0; jj < 4; jj++)
            #pragma unroll
            for (int e = 0; e < 4; e++) acc[i][jj][e] = 0.f;

    const int nc = K / KC;

    auto load_stage = [&](int c) {
        const int buf = c % NSTG;
        const bf16* gs[4] = {
            Ahi + (size_t)bm * lda + koff + c * KC,
            Alo + (size_t)bm * lda + koff + c * KC,
            Bhi + (size_t)bn * lda + koff + c * KC,
            Blo + (size_t)bn * lda + koff + c * KC };
        #pragma unroll
        for (int op = 0; op < 4; op++) {
            #pragma unroll
            for (int l = 0; l < 2; l++) {
                const int idx = tid + l * 256;
                const int r = idx >> 2, c8 = idx & 3;     // coalesced 64B/4thr
                const uint32_t dst = sb + buf * STB + op * OPB +
                    (uint32_t)(r * ROWB + ((c8 ^ ((r >> 1) & 3)) << 4));
                cp16(dst, gs[op] + (size_t)r * lda + c8 * 8);
            }
        }
        asm volatile("cp.async.commit_group;" ::: "memory");
    };

    load_stage(0);
    if (nc > 1) load_stage(1);

    for (int c = 0; c < nc; c++) {
        if (c < nc - 1) {
            asm volatile("cp.async.wait_group 1;" ::: "memory");
        } else {
            asm volatile("cp.async.wait_group 0;" ::: "memory");
        }
        __syncthreads();
        if (c + 2 < nc) load_stage(c + 2);

        const uint32_t st = sb + (c % NSTG) * STB;
        const uint32_t aB = st + (uint32_t)(wm * 64 * ROWB);
        const uint32_t bB = st + 2 * OPB + (uint32_t)(wn * 32 * ROWB);

        #pragma unroll
        for (int k16 = 0; k16 < 2; k16++) {
            const uint32_t lo = loff[k16];
            uint32_t bh[4][2], bl[4][2];
            #pragma unroll
            for (int ntp = 0; ntp < 2; ntp++) {
                const uint32_t nb = bB + (uint32_t)(ntp * 16 * ROWB) + lo;
                ldsm4(bh[2*ntp][0], bh[2*ntp+1][0], bh[2*ntp][1], bh[2*ntp+1][1], nb);
                ldsm4(bl[2*ntp][0], bl[2*ntp+1][0], bl[2*ntp][1], bl[2*ntp+1][1], nb + OPB);
            }
            uint32_t ah[2][4], al[2][4];
            ldsm4(ah[0][0], ah[0][1], ah[0][2], ah[0][3], aB + lo);
            ldsm4(al[0][0], al[0][1], al[0][2], al[0][3], aB + OPB + lo);
            #pragma unroll
            for (int mt = 0; mt < 4; mt++) {
                const int cur = mt & 1, nxt = cur ^ 1;
                if (mt < 3) {
                    const uint32_t ab = aB + (uint32_t)((mt + 1) * 16 * ROWB) + lo;
                    ldsm4(ah[nxt][0], ah[nxt][1], ah[nxt][2], ah[nxt][3], ab);
                    ldsm4(al[nxt][0], al[nxt][1], al[nxt][2], al[nxt][3], ab + OPB);
                }
                #pragma unroll
                for (int nt = 0; nt < 4; nt++) {
                    mma_bf16(acc[mt][nt], ah[cur], bh[nt]);
                    mma_bf16(acc[mt][nt], ah[cur], bl[nt]);
                    mma_bf16(acc[mt][nt], al[cur], bh[nt]);
                }
            }
        }
    }

    // -------- epilogue --------
    const size_t zoff = (EPI == 2) ? (size_t)blockIdx.z * 65536 : 0;
    #pragma unroll
    for (int mt = 0; mt < 4; mt++) {
        #pragma unroll
        for (int nt = 0; nt < 4; nt++) {
            const int row = bm + wm * 64 + mt * 16 + lr;
            const int col = bn + wn * 32 + nt * 8 + lc * 2;
            float v0 = acc[mt][nt][0], v1 = acc[mt][nt][1];
            float v2 = acc[mt][nt][2], v3 = acc[mt][nt][3];
            if (EPI == 0 && bias) {
                const float b0 = __ldg(bias + col), b1 = __ldg(bias + col + 1);
                v0 += b0; v1 += b1; v2 += b0; v3 += b1;
            }
            if (EPI != 1) {
                *(float2*)(C + zoff + (size_t)row * ldc + col)       = make_float2(v0, v1);
                *(float2*)(C + zoff + (size_t)(row + 8) * ldc + col) = make_float2(v2, v3);
            } else {
                float vv[4] = {v0, v1, v2, v3};
                uint32_t hp[2], lp[2];
                #pragma unroll
                for (int e = 0; e < 4; e++) {
                    uint32_t hb, lb;
                    split1(vv[e], hb, lb);
                    if (e & 1) { hp[e >> 1] |= hb << 16; lp[e >> 1] |= lb << 16; }
                    else       { hp[e >> 1]  = hb;       lp[e >> 1]  = lb; }
                }
                *(uint32_t*)(Chi + (size_t)row * ldc + col)       = hp[0];
                *(uint32_t*)(Chi + (size_t)(row + 8) * ldc + col) = hp[1];
                *(uint32_t*)(Clo + (size_t)row * ldc + col)       = lp[0];
                *(uint32_t*)(Clo + (size_t)(row + 8) * ldc + col) = lp[1];
            }
        }
    }
}

// ---------------- fused conversion kernel (ONE launch) ---------------------
// [0,4096) x split | 96 W1 ts | 192 W2 ts | 512 fc2 ts | 512 fc1 ew split
// | 256 b12 = fc1_b @ fc2_w + fc2_b
__global__ __launch_bounds__(256) void conv_all(
    const float* __restrict__ x, bf16* __restrict__ xhi, bf16* __restrict__ xlo,
    const float* __restrict__ W1, const float* __restrict__ W2,
    const float* __restrict__ fc1w, const float* __restrict__ fc2w,
    const float* __restrict__ fc1b, const float* __restrict__ fc2b,
    bf16* __restrict__ w1h, bf16* __restrict__ w1l,
    bf16* __restrict__ w2h, bf16* __restrict__ w2l,
    bf16* __restrict__ f2h, bf16* __restrict__ f2l,
    bf16* __restrict__ f1ah, bf16* __restrict__ f1al,
    float* __restrict__ b12)
{
    __shared__ float tile[32][33];
    const int tid = threadIdx.x;
    int b = blockIdx.x;

    if (b < 4096) {                       // x split
        const int i = b * 256 + tid;
        float4 v = ((const float4*)x)[i];
        float vv[4] = {v.x, v.y, v.z, v.w};
        uint32_t hp[2], lp[2];
        #pragma unroll
        for (int e = 0; e < 4; e++) {
            uint32_t hb, lb;
            split1(vv[e], hb, lb);
            if (e & 1) { hp[e >> 1] |= hb << 16; lp[e >> 1] |= lb << 16; }
            else       { hp[e >> 1]  = hb;       lp[e >> 1]  = lb; }
        }
        ((uint2*)xhi)[i] = make_uint2(hp[0], hp[1]);
        ((uint2*)xlo)[i] = make_uint2(lp[0], lp[1]);
        return;
    }
    b -= 4096;

    if (b >= 800 && b < 1312) {           // fc1_w elementwise split (512)
        const int i = (b - 800) * 256 + tid;     // 131072 float4s
        float4 v = ((const float4*)fc1w)[i];
        float vv[4] = {v.x, v.y, v.z, v.w};
        uint32_t hp[2], lp[2];
        #pragma unroll
        for (int e = 0; e < 4; e++) {
            uint32_t hb, lb;
            split1(vv[e], hb, lb);
            if (e & 1) { hp[e >> 1] |= hb << 16; lp[e >> 1] |= lb << 16; }
            else       { hp[e >> 1]  = hb;       lp[e >> 1]  = lb; }
        }
        ((uint2*)f1ah)[i] = make_uint2(hp[0], hp[1]);
        ((uint2*)f1al)[i] = make_uint2(lp[0], lp[1]);
        return;
    }
    if (b >= 1312) {                      // b12 (256 blocks, one n each)
        const int n = b - 1312;
        float s = 0.f;
        for (int k = tid; k < HIDDEN; k += 256)
            s += fc1b[k] * fc2w[(size_t)k * 256 + n];
        float* red = &tile[0][0];
        red[tid] = s;
        __syncthreads();
        for (int w = 128; w > 0; w >>= 1) {
            if (tid < w) red[tid] += red[tid + w];
            __syncthreads();
        }
        if (tid == 0) b12[n] = red[0] + fc2b[n];
        return;
    }

    const float* B; bf16 *Th, *Tl;
    int K, N, n_off, out_ld, bx, by;
    if (b < 96) {                          // W1 transpose-split
        const int q = b / 32, r = b % 32;
        B = W1 + (size_t)q * 128 * 256; Th = w1h; Tl = w1l;
        K = 128; N = 256; n_off = q * 256; out_ld = 128;
        bx = r % 8; by = r / 8;
    } else if (b < 288) {                  // W2 transpose-split
        b -= 96;
        const int q = b / 64, r = b % 64;
        B = W2 + (size_t)q * 256 * 256; Th = w2h; Tl = w2l;
        K = 256; N = 256; n_off = q * 256; out_ld = 256;
        bx = r % 8; by = r / 8;
    } else {                               // fc2_w transpose-split (512)
        b -= 288;
        B = fc2w; Th = f2h; Tl = f2l;
        K = 2048; N = 256; n_off = 0; out_ld = 2048;
        bx = b % 8; by = b / 8;
    }

    const int n0 = bx * 32, k0 = by * 32;
    const int tx = tid & 31, ty = tid >> 5;
    #pragma unroll
    for (int i = 0; i < 4; i++) {
        const int r = ty + i * 8;
        tile[r][tx] = B[(size_t)(k0 + r) * N + n0 + tx];
    }
    __syncthreads();
    #pragma unroll
    for (int i = 0; i < 4; i++) {
        const int n = ty + i * 8;
        const float v = tile[tx][n];
        uint32_t hb, lb;
        split1(v, hb, lb);
        const size_t o = (size_t)(n_off + n0 + n) * out_ld + k0 + tx;
        Th[o] = __ushort_as_bfloat16((unsigned short)hb);
        Tl[o] = __ushort_as_bfloat16((unsigned short)lb);
    }
}

// ---------------- W12 partial reduce + split (deterministic) ---------------
__global__ __launch_bounds__(256) void w12_reduce_split(
    const float* __restrict__ w12p, bf16* __restrict__ w12h, bf16* __restrict__ w12l)
{
    const int i = blockIdx.x * 256 + threadIdx.x;     // float4 index, 16384 total
    float4 s = ((const float4*)w12p)[i];
    #pragma unroll
    for (int z = 1; z < 8; z++) {
        float4 p = ((const float4*)w12p)[z * 16384 + i];
        s.x += p.x; s.y += p.y; s.z += p.z; s.w += p.w;
    }
    float vv[4] = {s.x, s.y, s.z, s.w};
    uint32_t hp[2], lp[2];
    #pragma unroll
    for (int e = 0; e < 4; e++) {
        uint32_t hb, lb;
        split1(vv[e], hb, lb);
        if (e & 1) { hp[e >> 1] |= hb << 16; lp[e >> 1] |= lb << 16; }
        else       { hp[e >> 1]  = hb;       lp[e >> 1]  = lb; }
    }
    ((uint2*)w12h)[i] = make_uint2(hp[0], hp[1]);
    ((uint2*)w12l)[i] = make_uint2(lp[0], lp[1]);
}

// ---------------- attention (f32x2 packed FMA, no-max softmax) -------------
__device__ __forceinline__ void write_split16(const float* o, float inv,
                                              bf16* Hb, bf16* Lb, size_t off)
{
    uint32_t hp[8], lp[8];
    #pragma unroll
    for (int b = 0; b < 16; b++) {
        uint32_t hb, lb;
        split1(o[b] * inv, hb, lb);
        if (b & 1) { hp[b >> 1] |= hb << 16; lp[b >> 1] |= lb << 16; }
        else       { hp[b >> 1]  = hb;       lp[b >> 1]  = lb; }
    }
    *(uint4*)(Hb + off)     = make_uint4(hp[0], hp[1], hp[2], hp[3]);
    *(uint4*)(Hb + off + 8) = make_uint4(hp[4], hp[5], hp[6], hp[7]);
    *(uint4*)(Lb + off)     = make_uint4(lp[0], lp[1], lp[2], lp[3]);
    *(uint4*)(Lb + off + 8) = make_uint4(lp[4], lp[5], lp[6], lp[7]);
}

template <int SEQ>
__device__ __forceinline__ void attn_body(
    const float* __restrict__ base,
    float (*ks)[16], float (*vs)[16],
    float* o, float& l, const int me)
{
    u64 q2[8];
    #pragma unroll
    for (int c = 0; c < 4; c++) {
        ulonglong2 qq = *(const ulonglong2*)(base + c * 4);
        q2[c * 2] = qq.x; q2[c * 2 + 1] = qq.y;
        *(float4*)(&ks[me][c * 4]) = *(const float4*)(base + 256 + c * 4);
        *(float4*)(&vs[me][c * 4]) = *(const float4*)(base + 512 + c * 4);
    }
    __syncthreads();

    u64 o2[8];
    #pragma unroll
    for (int p = 0; p < 8; p++) o2[p] = 0ULL;
    l = 0.f;

    for (int I = 0; I < SEQ; I++) {
        const ulonglong2* kp = (const ulonglong2*)ks[I];
        ulonglong2 ka = kp[0], kb = kp[1], kc = kp[2], kd = kp[3];
        u64 a0 = fma2(q2[0], ka.x, 0ULL);
        u64 a1 = fma2(q2[1], ka.y, 0ULL);
        a0 = fma2(q2[2], kb.x, a0);
        a1 = fma2(q2[3], kb.y, a1);
        a0 = fma2(q2[4], kc.x, a0);
        a1 = fma2(q2[5], kc.y, a1);
        a0 = fma2(q2[6], kd.x, a0);
        a1 = fma2(q2[7], kd.y, a1);
        a0 = add2(a0, a1);
        float s0, s1;
        unpack2(a0, s0, s1);
        const float e = __expf(s0 + s1);
        l += e;
        const u64 e2 = pack2(e, e);
        const ulonglong2* vp = (const ulonglong2*)vs[I];
        ulonglong2 va = vp[0], vb = vp[1], vc = vp[2], vd = vp[3];
        o2[0] = fma2(e2, va.x, o2[0]);
        o2[1] = fma2(e2, va.y, o2[1]);
        o2[2] = fma2(e2, vb.x, o2[2]);
        o2[3] = fma2(e2, vb.y, o2[3]);
        o2[4] = fma2(e2, vc.x, o2[4]);
        o2[5] = fma2(e2, vc.y, o2[5]);
        o2[6] = fma2(e2, vd.x, o2[6]);
        o2[7] = fma2(e2, vd.y, o2[7]);
    }
    #pragma unroll
    for (int p = 0; p < 8; p++) unpack2(o2[p], o[2 * p], o[2 * p + 1]);
}

__global__ __launch_bounds__(128) void temporal_attn(
    const float* __restrict__ y1, bf16* __restrict__ tH, bf16* __restrict__ tL)
{
    const int j = blockIdx.x, a = blockIdx.y, i = threadIdx.x;
    __shared__ float ks[128][16];
    __shared__ float vs[128][16];
    const float* base = y1 + ((size_t)i * 256 + j) * 768 + a * 16;
    float o[16], l;
    attn_body<128>(base, ks, vs, o, l, i);
    write_split16(o, 1.f / l, tH, tL, ((size_t)i * 256 + j) * 256 + a * 16);
}

__global__ __launch_bounds__(256) void point_attn(
    const float* __restrict__ y2, bf16* __restrict__ pH, bf16* __restrict__ pL)
{
    const int i = blockIdx.x, a = blockIdx.y, j = threadIdx.x;
    __shared__ float ks[256][16];
    __shared__ float vs[256][16];
    const float* base = y2 + ((size_t)i * 256 + j) * 768 + a * 16;
    float o[16], l;
    attn_body<256>(base, ks, vs, o, l, j);
    write_split16(o, 1.f / l, pH, pL, ((size_t)i * 256 + j) * 256 + a * 16);
}

// ---------------------------------------------------------------------------
extern "C" void kernel_launch(void* const* d_in, const int* in_sizes, int n_in,
                              void* d_out, int out_size)
{
    const float* x     = (const float*)d_in[0];
    const float* W1    = (const float*)d_in[1];
    const float* W2    = (const float*)d_in[2];
    const float* fc1_w = (const float*)d_in[3];
    const float* fc1_b = (const float*)d_in[4];
    const float* fc2_w = (const float*)d_in[5];
    const float* fc2_b = (const float*)d_in[6];
    float* out = (float*)d_out;

    bf16 *xhi, *xlo, *thi, *tlo, *pahi, *palo;
    bf16 *w1h, *w1l, *w2h, *w2l, *f2h, *f2l, *f1ah, *f1al, *w12h, *w12l;
    float *y1, *y2, *w12p, *b12;
    cudaGetSymbolAddress((void**)&xhi, g_xhi);   cudaGetSymbolAddress((void**)&xlo, g_xlo);
    cudaGetSymbolAddress((void**)&y1, g_y1);     cudaGetSymbolAddress((void**)&y2, g_y2);
    cudaGetSymbolAddress((void**)&thi, g_thi);   cudaGetSymbolAddress((void**)&tlo, g_tlo);
    cudaGetSymbolAddress((void**)&pahi, g_pahi); cudaGetSymbolAddress((void**)&palo, g_palo);
    cudaGetSymbolAddress((void**)&w1h, g_w1t_hi); cudaGetSymbolAddress((void**)&w1l, g_w1t_lo);
    cudaGetSymbolAddress((void**)&w2h, g_w2t_hi); cudaGetSymbolAddress((void**)&w2l, g_w2t_lo);
    cudaGetSymbolAddress((void**)&f2h, g_f2t_hi); cudaGetSymbolAddress((void**)&f2l, g_f2t_lo);
    cudaGetSymbolAddress((void**)&f1ah, g_f1a_hi); cudaGetSymbolAddress((void**)&f1al, g_f1a_lo);
    cudaGetSymbolAddress((void**)&w12p, g_w12p);
    cudaGetSymbolAddress((void**)&w12h, g_w12h); cudaGetSymbolAddress((void**)&w12l, g_w12l);
    cudaGetSymbolAddress((void**)&b12, g_b12);

    cudaFuncSetAttribute(gemm_mma<0>, cudaFuncAttributeMaxDynamicSharedMemorySize, SMEM_BYTES);
    cudaFuncSetAttribute(gemm_mma<1>, cudaFuncAttributeMaxDynamicSharedMemorySize, SMEM_BYTES);
    cudaFuncSetAttribute(gemm_mma<2>, cudaFuncAttributeMaxDynamicSharedMemorySize, SMEM_BYTES);

    // 0) conversions + b12
    conv_all<<<5664, 256>>>(x, xhi, xlo, W1, W2, fc1_w, fc2_w, fc1_b, fc2_b,
                            w1h, w1l, w2h, w2l, f2h, f2l, f1ah, f1al, b12);
    // 1) W12T = fc2_w^T @ fc1_w^T  (split-K=8 partials)
    gemm_mma<2><<<dim3(2, 2, 8), 256, SMEM_BYTES>>>(
        f2h, f2l, f1ah, f1al, w12p, nullptr, nullptr, nullptr, 256, 256, 2048);
    // 2) reduce partials + split
    w12_reduce_split<<<64, 256>>>(w12p, w12h, w12l);
    // 3) QKV1
    gemm_mma<0><<<dim3(768 / TN, ROWS / TM), 256, SMEM_BYTES>>>(
        xhi, xlo, w1h, w1l, y1, nullptr, nullptr, nullptr, 128, 768, 128);
    // 4) temporal attention
    temporal_attn<<<dim3(PP, HD), 128>>>(y1, thi, tlo);
    // 5) QKV2   [launch index 5: ncu capture target]
    gemm_mma<0><<<dim3(768 / TN, ROWS / TM), 256, SMEM_BYTES>>>(
        thi, tlo, w2h, w2l, y2, nullptr, nullptr, nullptr, 256, 768, 256);
    // 6) point attention
    point_attn<<<dim3(NN, HD), 256>>>(y2, pahi, palo);
    // 7) fused FC: out = pa @ W12 + b12
    gemm_mma<0><<<dim3(256 / TN, ROWS / TM), 256, SMEM_BYTES>>>(
        pahi, palo, w12h, w12l, out, nullptr, nullptr, b12, 256, 256, 256);
}

// round 12
// speedup vs baseline: 2.6823x; 1.1069x over previous
#include <cuda_runtime.h>
#include <cuda_bf16.h>
#include <cstdint>

typedef __nv_bfloat16 bf16;
typedef unsigned long long u64;

#define NN 128
#define PP 256
#define DD 128
#define HD 16
#define ROWS (NN*PP)      // 32768
#define HIDDEN 2048

// ---------------- scratch (device globals; no cudaMalloc allowed) ----------
__device__ bf16  g_xhi[(size_t)ROWS * DD],    g_xlo[(size_t)ROWS * DD];
__device__ float g_y1 [(size_t)ROWS * 768];
__device__ bf16  g_thi[(size_t)ROWS * 256],   g_tlo[(size_t)ROWS * 256];
__device__ float g_y2 [(size_t)ROWS * 768];
__device__ bf16  g_pahi[(size_t)ROWS * 256],  g_palo[(size_t)ROWS * 256];
// transposed split weights: Bt[n][k]
__device__ bf16  g_w1t_hi[768 * 128],   g_w1t_lo[768 * 128];
__device__ bf16  g_w2t_hi[768 * 256],   g_w2t_lo[768 * 256];
__device__ bf16  g_f2t_hi[256 * 2048],  g_f2t_lo[256 * 2048];   // fc2_w^T split
__device__ bf16  g_f1a_hi[256 * 2048],  g_f1a_lo[256 * 2048];   // fc1_w row-major split
// fused FC weight: W12T = fc2_w^T @ fc1_w^T (split-K partials, then split)
__device__ float g_w12p[8 * 256 * 256];
__device__ bf16  g_w12h[256 * 256],     g_w12l[256 * 256];
__device__ float g_b12[256];

// ---------------- helpers ---------------------------------------------------
__device__ __forceinline__ uint32_t smem_u32(const void* p) {
    uint32_t a;
    asm("{ .reg .u64 t; cvta.to.shared.u64 t, %1; cvt.u32.u64 %0, t; }"
        : "=r"(a) : "l"(p));
    return a;
}
__device__ __forceinline__ void cp16(uint32_t dst, const void* src) {
    asm volatile("cp.async.cg.shared.global [%0], [%1], 16;"
                 :: "r"(dst), "l"(src) : "memory");
}
__device__ __forceinline__ void mma_bf16(float* d, const uint32_t* a, const uint32_t* b) {
    asm volatile(
        "mma.sync.aligned.m16n8k16.row.col.f32.bf16.bf16.f32 "
        "{%0,%1,%2,%3}, {%4,%5,%6,%7}, {%8,%9}, {%0,%1,%2,%3};"
        : "+f"(d[0]), "+f"(d[1]), "+f"(d[2]), "+f"(d[3])
        : "r"(a[0]), "r"(a[1]), "r"(a[2]), "r"(a[3]), "r"(b[0]), "r"(b[1]));
}
__device__ __forceinline__ void ldsm4(uint32_t& r0, uint32_t& r1, uint32_t& r2,
                                      uint32_t& r3, uint32_t addr) {
    asm volatile("ldmatrix.sync.aligned.m8n8.x4.shared.b16 {%0,%1,%2,%3}, [%4];"
                 : "=r"(r0), "=r"(r1), "=r"(r2), "=r"(r3) : "r"(addr));
}
// packed f32x2 (Blackwell FFMA2 path)
__device__ __forceinline__ u64 fma2(u64 a, u64 b, u64 c) {
    u64 d; asm("fma.rn.f32x2 %0, %1, %2, %3;" : "=l"(d) : "l"(a), "l"(b), "l"(c));
    return d;
}
__device__ __forceinline__ u64 add2(u64 a, u64 b) {
    u64 d; asm("add.rn.f32x2 %0, %1, %2;" : "=l"(d) : "l"(a), "l"(b));
    return d;
}
__device__ __forceinline__ u64 pack2(float a, float b) {
    u64 d; asm("mov.b64 %0, {%1, %2};" : "=l"(d)
               : "r"(__float_as_uint(a)), "r"(__float_as_uint(b)));
    return d;
}
__device__ __forceinline__ void unpack2(u64 v, float& a, float& b) {
    uint32_t x, y;
    asm("mov.b64 {%0, %1}, %2;" : "=r"(x), "=r"(y) : "l"(v));
    a = __uint_as_float(x); b = __uint_as_float(y);
}
__device__ __forceinline__ void split1(float v, uint32_t& hb, uint32_t& lb) {
    bf16 h = __float2bfloat16(v);
    bf16 l = __float2bfloat16(v - __bfloat162float(h));
    hb = (uint32_t)__bfloat16_as_ushort(h);
    lb = (uint32_t)__bfloat16_as_ushort(l);
}

// ---------------- split-bf16 mma.sync GEMM ---------------------------------
#define TM 128
#define TN 128
#define KC 32
#define ROWB 64
#define OPB (128 * ROWB)
#define STB (4 * OPB)
#define NSTG 3
#define SMEM_BYTES (NSTG * STB)      // 98304

template <int EPI>
__global__ __launch_bounds__(256, 2) void gemm_mma(
    const bf16* __restrict__ Ahi, const bf16* __restrict__ Alo,
    const bf16* __restrict__ Bhi, const bf16* __restrict__ Blo,
    float* __restrict__ C, bf16* __restrict__ Chi, bf16* __restrict__ Clo,
    const float* __restrict__ bias, int K, int ldc, int lda)
{
    extern __shared__ char smem[];
    const uint32_t sb = smem_u32(smem);
    const int tid = threadIdx.x, lane = tid & 31, wid = tid >> 5;
    const int wm = wid >> 2, wn = wid & 3;
    const int bn = blockIdx.x * TN, bm = blockIdx.y * TM;
    const int lr = lane >> 2, lc = lane & 3;
    const int koff = (EPI == 2) ? (int)blockIdx.z * K : 0;

    const int j  = lane >> 3;
    const int rr = ((j & 1) << 3) + (lane & 7);
    const int xr = (rr >> 1) & 3;
    const int cj = j >> 1;
    uint32_t loff[2];
    loff[0] = (uint32_t)(rr * ROWB + (((0 + cj) ^ xr) << 4));
    loff[1] = (uint32_t)(rr * ROWB + (((2 + cj) ^ xr) << 4));

    float acc[4][4][4];
    #pragma unroll
    for (int i = 0; i < 4; i++)
        #pragma unroll
        for (int jj = 0; jj < 4; jj++)
            #pragma unroll
            for (int e = 0; e < 4; e++) acc[i][jj][e] = 0.f;

    const int nc = K / KC;

    auto load_stage = [&](int c) {
        const int buf = c % NSTG;
        const bf16* gs[4] = {
            Ahi + (size_t)bm * lda + koff + c * KC,
            Alo + (size_t)bm * lda + koff + c * KC,
            Bhi + (size_t)bn * lda + koff + c * KC,
            Blo + (size_t)bn * lda + koff + c * KC };
        #pragma unroll
        for (int op = 0; op < 4; op++) {
            #pragma unroll
            for (int l = 0; l < 2; l++) {
                const int idx = tid + l * 256;
                const int r = idx >> 2, c8 = idx & 3;     // coalesced 64B/4thr
                const uint32_t dst = sb + buf * STB + op * OPB +
                    (uint32_t)(r * ROWB + ((c8 ^ ((r >> 1) & 3)) << 4));
                cp16(dst, gs[op] + (size_t)r * lda + c8 * 8);
            }
        }
        asm volatile("cp.async.commit_group;" ::: "memory");
    };

    load_stage(0);
    if (nc > 1) load_stage(1);

    for (int c = 0; c < nc; c++) {
        if (c < nc - 1) {
            asm volatile("cp.async.wait_group 1;" ::: "memory");
        } else {
            asm volatile("cp.async.wait_group 0;" ::: "memory");
        }
        __syncthreads();
        if (c + 2 < nc) load_stage(c + 2);

        const uint32_t st = sb + (c % NSTG) * STB;
        const uint32_t aB = st + (uint32_t)(wm * 64 * ROWB);
        const uint32_t bB = st + 2 * OPB + (uint32_t)(wn * 32 * ROWB);

        #pragma unroll
        for (int k16 = 0; k16 < 2; k16++) {
            const uint32_t lo = loff[k16];
            uint32_t bh[4][2], bl[4][2];
            #pragma unroll
            for (int ntp = 0; ntp < 2; ntp++) {
                const uint32_t nb = bB + (uint32_t)(ntp * 16 * ROWB) + lo;
                ldsm4(bh[2*ntp][0], bh[2*ntp+1][0], bh[2*ntp][1], bh[2*ntp+1][1], nb);
                ldsm4(bl[2*ntp][0], bl[2*ntp+1][0], bl[2*ntp][1], bl[2*ntp+1][1], nb + OPB);
            }
            uint32_t ah[2][4], al[2][4];
            ldsm4(ah[0][0], ah[0][1], ah[0][2], ah[0][3], aB + lo);
            ldsm4(al[0][0], al[0][1], al[0][2], al[0][3], aB + OPB + lo);
            #pragma unroll
            for (int mt = 0; mt < 4; mt++) {
                const int cur = mt & 1, nxt = cur ^ 1;
                if (mt < 3) {
                    const uint32_t ab = aB + (uint32_t)((mt + 1) * 16 * ROWB) + lo;
                    ldsm4(ah[nxt][0], ah[nxt][1], ah[nxt][2], ah[nxt][3], ab);
                    ldsm4(al[nxt][0], al[nxt][1], al[nxt][2], al[nxt][3], ab + OPB);
                }
                #pragma unroll
                for (int nt = 0; nt < 4; nt++) {
                    mma_bf16(acc[mt][nt], ah[cur], bh[nt]);
                    mma_bf16(acc[mt][nt], ah[cur], bl[nt]);
                    mma_bf16(acc[mt][nt], al[cur], bh[nt]);
                }
            }
        }
    }

    const size_t zoff = (EPI == 2) ? (size_t)blockIdx.z * 65536 : 0;
    #pragma unroll
    for (int mt = 0; mt < 4; mt++) {
        #pragma unroll
        for (int nt = 0; nt < 4; nt++) {
            const int row = bm + wm * 64 + mt * 16 + lr;
            const int col = bn + wn * 32 + nt * 8 + lc * 2;
            float v0 = acc[mt][nt][0], v1 = acc[mt][nt][1];
            float v2 = acc[mt][nt][2], v3 = acc[mt][nt][3];
            if (EPI == 0 && bias) {
                const float b0 = __ldg(bias + col), b1 = __ldg(bias + col + 1);
                v0 += b0; v1 += b1; v2 += b0; v3 += b1;
            }
            if (EPI != 1) {
                *(float2*)(C + zoff + (size_t)row * ldc + col)       = make_float2(v0, v1);
                *(float2*)(C + zoff + (size_t)(row + 8) * ldc + col) = make_float2(v2, v3);
            } else {
                float vv[4] = {v0, v1, v2, v3};
                uint32_t hp[2], lp[2];
                #pragma unroll
                for (int e = 0; e < 4; e++) {
                    uint32_t hb, lb;
                    split1(vv[e], hb, lb);
                    if (e & 1) { hp[e >> 1] |= hb << 16; lp[e >> 1] |= lb << 16; }
                    else       { hp[e >> 1]  = hb;       lp[e >> 1]  = lb; }
                }
                *(uint32_t*)(Chi + (size_t)row * ldc + col)       = hp[0];
                *(uint32_t*)(Chi + (size_t)(row + 8) * ldc + col) = hp[1];
                *(uint32_t*)(Clo + (size_t)row * ldc + col)       = lp[0];
                *(uint32_t*)(Clo + (size_t)(row + 8) * ldc + col) = lp[1];
            }
        }
    }
}

// ---------------- fused conversion kernel (ONE launch) ---------------------
__global__ __launch_bounds__(256) void conv_all(
    const float* __restrict__ x, bf16* __restrict__ xhi, bf16* __restrict__ xlo,
    const float* __restrict__ W1, const float* __restrict__ W2,
    const float* __restrict__ fc1w, const float* __restrict__ fc2w,
    const float* __restrict__ fc1b, const float* __restrict__ fc2b,
    bf16* __restrict__ w1h, bf16* __restrict__ w1l,
    bf16* __restrict__ w2h, bf16* __restrict__ w2l,
    bf16* __restrict__ f2h, bf16* __restrict__ f2l,
    bf16* __restrict__ f1ah, bf16* __restrict__ f1al,
    float* __restrict__ b12)
{
    __shared__ float tile[32][33];
    const int tid = threadIdx.x;
    int b = blockIdx.x;

    if (b < 4096) {                       // x split
        const int i = b * 256 + tid;
        float4 v = ((const float4*)x)[i];
        float vv[4] = {v.x, v.y, v.z, v.w};
        uint32_t hp[2], lp[2];
        #pragma unroll
        for (int e = 0; e < 4; e++) {
            uint32_t hb, lb;
            split1(vv[e], hb, lb);
            if (e & 1) { hp[e >> 1] |= hb << 16; lp[e >> 1] |= lb << 16; }
            else       { hp[e >> 1]  = hb;       lp[e >> 1]  = lb; }
        }
        ((uint2*)xhi)[i] = make_uint2(hp[0], hp[1]);
        ((uint2*)xlo)[i] = make_uint2(lp[0], lp[1]);
        return;
    }
    b -= 4096;

    if (b >= 800 && b < 1312) {           // fc1_w elementwise split (512)
        const int i = (b - 800) * 256 + tid;
        float4 v = ((const float4*)fc1w)[i];
        float vv[4] = {v.x, v.y, v.z, v.w};
        uint32_t hp[2], lp[2];
        #pragma unroll
        for (int e = 0; e < 4; e++) {
            uint32_t hb, lb;
            split1(vv[e], hb, lb);
            if (e & 1) { hp[e >> 1] |= hb << 16; lp[e >> 1] |= lb << 16; }
            else       { hp[e >> 1]  = hb;       lp[e >> 1]  = lb; }
        }
        ((uint2*)f1ah)[i] = make_uint2(hp[0], hp[1]);
        ((uint2*)f1al)[i] = make_uint2(lp[0], lp[1]);
        return;
    }
    if (b >= 1312) {                      // b12 (256 blocks, one n each)
        const int n = b - 1312;
        float s = 0.f;
        for (int k = tid; k < HIDDEN; k += 256)
            s += fc1b[k] * fc2w[(size_t)k * 256 + n];
        float* red = &tile[0][0];
        red[tid] = s;
        __syncthreads();
        for (int w = 128; w > 0; w >>= 1) {
            if (tid < w) red[tid] += red[tid + w];
            __syncthreads();
        }
        if (tid == 0) b12[n] = red[0] + fc2b[n];
        return;
    }

    const float* B; bf16 *Th, *Tl;
    int K, N, n_off, out_ld, bx, by;
    if (b < 96) {                          // W1 transpose-split
        const int q = b / 32, r = b % 32;
        B = W1 + (size_t)q * 128 * 256; Th = w1h; Tl = w1l;
        K = 128; N = 256; n_off = q * 256; out_ld = 128;
        bx = r % 8; by = r / 8;
    } else if (b < 288) {                  // W2 transpose-split
        b -= 96;
        const int q = b / 64, r = b % 64;
        B = W2 + (size_t)q * 256 * 256; Th = w2h; Tl = w2l;
        K = 256; N = 256; n_off = q * 256; out_ld = 256;
        bx = r % 8; by = r / 8;
    } else {                               // fc2_w transpose-split (512)
        b -= 288;
        B = fc2w; Th = f2h; Tl = f2l;
        K = 2048; N = 256; n_off = 0; out_ld = 2048;
        bx = b % 8; by = b / 8;
    }

    const int n0 = bx * 32, k0 = by * 32;
    const int tx = tid & 31, ty = tid >> 5;
    #pragma unroll
    for (int i = 0; i < 4; i++) {
        const int r = ty + i * 8;
        tile[r][tx] = B[(size_t)(k0 + r) * N + n0 + tx];
    }
    __syncthreads();
    #pragma unroll
    for (int i = 0; i < 4; i++) {
        const int n = ty + i * 8;
        const float v = tile[tx][n];
        uint32_t hb, lb;
        split1(v, hb, lb);
        const size_t o = (size_t)(n_off + n0 + n) * out_ld + k0 + tx;
        Th[o] = __ushort_as_bfloat16((unsigned short)hb);
        Tl[o] = __ushort_as_bfloat16((unsigned short)lb);
    }
}

// ---------------- W12 partial reduce + split -------------------------------
__global__ __launch_bounds__(256) void w12_reduce_split(
    const float* __restrict__ w12p, bf16* __restrict__ w12h, bf16* __restrict__ w12l)
{
    const int i = blockIdx.x * 256 + threadIdx.x;
    float4 s = ((const float4*)w12p)[i];
    #pragma unroll
    for (int z = 1; z < 8; z++) {
        float4 p = ((const float4*)w12p)[z * 16384 + i];
        s.x += p.x; s.y += p.y; s.z += p.z; s.w += p.w;
    }
    float vv[4] = {s.x, s.y, s.z, s.w};
    uint32_t hp[2], lp[2];
    #pragma unroll
    for (int e = 0; e < 4; e++) {
        uint32_t hb, lb;
        split1(vv[e], hb, lb);
        if (e & 1) { hp[e >> 1] |= hb << 16; lp[e >> 1] |= lb << 16; }
        else       { hp[e >> 1]  = hb;       lp[e >> 1]  = lb; }
    }
    ((uint2*)w12h)[i] = make_uint2(hp[0], hp[1]);
    ((uint2*)w12l)[i] = make_uint2(lp[0], lp[1]);
}

// ---------------- attention: 2 queries/thread (LDS amortized) --------------
__device__ __forceinline__ void write_split16(const float* o, float inv,
                                              bf16* Hb, bf16* Lb, size_t off)
{
    uint32_t hp[8], lp[8];
    #pragma unroll
    for (int b = 0; b < 16; b++) {
        uint32_t hb, lb;
        split1(o[b] * inv, hb, lb);
        if (b & 1) { hp[b >> 1] |= hb << 16; lp[b >> 1] |= lb << 16; }
        else       { hp[b >> 1]  = hb;       lp[b >> 1]  = lb; }
    }
    *(uint4*)(Hb + off)     = make_uint4(hp[0], hp[1], hp[2], hp[3]);
    *(uint4*)(Hb + off + 8) = make_uint4(hp[4], hp[5], hp[6], hp[7]);
    *(uint4*)(Lb + off)     = make_uint4(lp[0], lp[1], lp[2], lp[3]);
    *(uint4*)(Lb + off + 8) = make_uint4(lp[4], lp[5], lp[6], lp[7]);
}

template <int SEQ>
__device__ __forceinline__ void attn_body2(
    const float* __restrict__ b0, const float* __restrict__ b1,
    float (*ks)[16], float (*vs)[16],
    float* o0, float* o1, float& l0, float& l1,
    const int me0, const int me1)
{
    u64 q0[8], q1[8];
    #pragma unroll
    for (int c = 0; c < 4; c++) {
        ulonglong2 qq = *(const ulonglong2*)(b0 + c * 4);
        q0[c * 2] = qq.x; q0[c * 2 + 1] = qq.y;
        *(float4*)(&ks[me0][c * 4]) = *(const float4*)(b0 + 256 + c * 4);
        *(float4*)(&vs[me0][c * 4]) = *(const float4*)(b0 + 512 + c * 4);
        ulonglong2 rr = *(const ulonglong2*)(b1 + c * 4);
        q1[c * 2] = rr.x; q1[c * 2 + 1] = rr.y;
        *(float4*)(&ks[me1][c * 4]) = *(const float4*)(b1 + 256 + c * 4);
        *(float4*)(&vs[me1][c * 4]) = *(const float4*)(b1 + 512 + c * 4);
    }
    __syncthreads();

    u64 oo0[8], oo1[8];
    #pragma unroll
    for (int p = 0; p < 8; p++) { oo0[p] = 0ULL; oo1[p] = 0ULL; }
    l0 = 0.f; l1 = 0.f;

    for (int I = 0; I < SEQ; I++) {
        const ulonglong2* kp = (const ulonglong2*)ks[I];
        ulonglong2 ka = kp[0], kb = kp[1], kc = kp[2], kd = kp[3];
        // dot for query 0
        u64 a0 = fma2(q0[0], ka.x, 0ULL);
        u64 a1 = fma2(q0[1], ka.y, 0ULL);
        a0 = fma2(q0[2], kb.x, a0);
        a1 = fma2(q0[3], kb.y, a1);
        a0 = fma2(q0[4], kc.x, a0);
        a1 = fma2(q0[5], kc.y, a1);
        a0 = fma2(q0[6], kd.x, a0);
        a1 = fma2(q0[7], kd.y, a1);
        a0 = add2(a0, a1);
        // dot for query 1
        u64 c0 = fma2(q1[0], ka.x, 0ULL);
        u64 c1 = fma2(q1[1], ka.y, 0ULL);
        c0 = fma2(q1[2], kb.x, c0);
        c1 = fma2(q1[3], kb.y, c1);
        c0 = fma2(q1[4], kc.x, c0);
        c1 = fma2(q1[5], kc.y, c1);
        c0 = fma2(q1[6], kd.x, c0);
        c1 = fma2(q1[7], kd.y, c1);
        c0 = add2(c0, c1);
        float s0, s1, s2, s3;
        unpack2(a0, s0, s1);
        unpack2(c0, s2, s3);
        const float e0 = __expf(s0 + s1);
        const float e1 = __expf(s2 + s3);
        l0 += e0; l1 += e1;
        const u64 ee0 = pack2(e0, e0);
        const u64 ee1 = pack2(e1, e1);
        const ulonglong2* vp = (const ulonglong2*)vs[I];
        ulonglong2 va = vp[0], vb = vp[1], vc = vp[2], vd = vp[3];
        oo0[0] = fma2(ee0, va.x, oo0[0]);  oo1[0] = fma2(ee1, va.x, oo1[0]);
        oo0[1] = fma2(ee0, va.y, oo0[1]);  oo1[1] = fma2(ee1, va.y, oo1[1]);
        oo0[2] = fma2(ee0, vb.x, oo0[2]);  oo1[2] = fma2(ee1, vb.x, oo1[2]);
        oo0[3] = fma2(ee0, vb.y, oo0[3]);  oo1[3] = fma2(ee1, vb.y, oo1[3]);
        oo0[4] = fma2(ee0, vc.x, oo0[4]);  oo1[4] = fma2(ee1, vc.x, oo1[4]);
        oo0[5] = fma2(ee0, vc.y, oo0[5]);  oo1[5] = fma2(ee1, vc.y, oo1[5]);
        oo0[6] = fma2(ee0, vd.x, oo0[6]);  oo1[6] = fma2(ee1, vd.x, oo1[6]);
        oo0[7] = fma2(ee0, vd.y, oo0[7]);  oo1[7] = fma2(ee1, vd.y, oo1[7]);
    }
    #pragma unroll
    for (int p = 0; p < 8; p++) {
        unpack2(oo0[p], o0[2 * p], o0[2 * p + 1]);
        unpack2(oo1[p], o1[2 * p], o1[2 * p + 1]);
    }
}

__global__ __launch_bounds__(64) void temporal_attn(
    const float* __restrict__ y1, bf16* __restrict__ tH, bf16* __restrict__ tL)
{
    const int j = blockIdx.x, a = blockIdx.y, t = threadIdx.x;
    __shared__ float ks[128][16];
    __shared__ float vs[128][16];
    const int i0 = t, i1 = t + 64;
    const float* b0 = y1 + ((size_t)i0 * 256 + j) * 768 + a * 16;
    const float* b1 = y1 + ((size_t)i1 * 256 + j) * 768 + a * 16;
    float o0[16], o1[16], l0, l1;
    attn_body2<128>(b0, b1, ks, vs, o0, o1, l0, l1, i0, i1);
    write_split16(o0, 1.f / l0, tH, tL, ((size_t)i0 * 256 + j) * 256 + a * 16);
    write_split16(o1, 1.f / l1, tH, tL, ((size_t)i1 * 256 + j) * 256 + a * 16);
}

__global__ __launch_bounds__(128) void point_attn(
    const float* __restrict__ y2, bf16* __restrict__ pH, bf16* __restrict__ pL)
{
    const int i = blockIdx.x, a = blockIdx.y, t = threadIdx.x;
    __shared__ float ks[256][16];
    __shared__ float vs[256][16];
    const int j0 = t, j1 = t + 128;
    const float* b0 = y2 + ((size_t)i * 256 + j0) * 768 + a * 16;
    const float* b1 = y2 + ((size_t)i * 256 + j1) * 768 + a * 16;
    float o0[16], o1[16], l0, l1;
    attn_body2<256>(b0, b1, ks, vs, o0, o1, l0, l1, j0, j1);
    write_split16(o0, 1.f / l0, pH, pL, ((size_t)i * 256 + j0) * 256 + a * 16);
    write_split16(o1, 1.f / l1, pH, pL, ((size_t)i * 256 + j1) * 256 + a * 16);
}

// ---------------------------------------------------------------------------
extern "C" void kernel_launch(void* const* d_in, const int* in_sizes, int n_in,
                              void* d_out, int out_size)
{
    const float* x     = (const float*)d_in[0];
    const float* W1    = (const float*)d_in[1];
    const float* W2    = (const float*)d_in[2];
    const float* fc1_w = (const float*)d_in[3];
    const float* fc1_b = (const float*)d_in[4];
    const float* fc2_w = (const float*)d_in[5];
    const float* fc2_b = (const float*)d_in[6];
    float* out = (float*)d_out;

    bf16 *xhi, *xlo, *thi, *tlo, *pahi, *palo;
    bf16 *w1h, *w1l, *w2h, *w2l, *f2h, *f2l, *f1ah, *f1al, *w12h, *w12l;
    float *y1, *y2, *w12p, *b12;
    cudaGetSymbolAddress((void**)&xhi, g_xhi);   cudaGetSymbolAddress((void**)&xlo, g_xlo);
    cudaGetSymbolAddress((void**)&y1, g_y1);     cudaGetSymbolAddress((void**)&y2, g_y2);
    cudaGetSymbolAddress((void**)&thi, g_thi);   cudaGetSymbolAddress((void**)&tlo, g_tlo);
    cudaGetSymbolAddress((void**)&pahi, g_pahi); cudaGetSymbolAddress((void**)&palo, g_palo);
    cudaGetSymbolAddress((void**)&w1h, g_w1t_hi); cudaGetSymbolAddress((void**)&w1l, g_w1t_lo);
    cudaGetSymbolAddress((void**)&w2h, g_w2t_hi); cudaGetSymbolAddress((void**)&w2l, g_w2t_lo);
    cudaGetSymbolAddress((void**)&f2h, g_f2t_hi); cudaGetSymbolAddress((void**)&f2l, g_f2t_lo);
    cudaGetSymbolAddress((void**)&f1ah, g_f1a_hi); cudaGetSymbolAddress((void**)&f1al, g_f1a_lo);
    cudaGetSymbolAddress((void**)&w12p, g_w12p);
    cudaGetSymbolAddress((void**)&w12h, g_w12h); cudaGetSymbolAddress((void**)&w12l, g_w12l);
    cudaGetSymbolAddress((void**)&b12, g_b12);

    cudaFuncSetAttribute(gemm_mma<0>, cudaFuncAttributeMaxDynamicSharedMemorySize, SMEM_BYTES);
    cudaFuncSetAttribute(gemm_mma<1>, cudaFuncAttributeMaxDynamicSharedMemorySize, SMEM_BYTES);
    cudaFuncSetAttribute(gemm_mma<2>, cudaFuncAttributeMaxDynamicSharedMemorySize, SMEM_BYTES);

    // 0) conversions + b12
    conv_all<<<5664, 256>>>(x, xhi, xlo, W1, W2, fc1_w, fc2_w, fc1_b, fc2_b,
                            w1h, w1l, w2h, w2l, f2h, f2l, f1ah, f1al, b12);
    // 1) W12T = fc2_w^T @ fc1_w^T  (split-K=8 partials)
    gemm_mma<2><<<dim3(2, 2, 8), 256, SMEM_BYTES>>>(
        f2h, f2l, f1ah, f1al, w12p, nullptr, nullptr, nullptr, 256, 256, 2048);
    // 2) reduce partials + split
    w12_reduce_split<<<64, 256>>>(w12p, w12h, w12l);
    // 3) QKV1
    gemm_mma<0><<<dim3(768 / TN, ROWS / TM), 256, SMEM_BYTES>>>(
        xhi, xlo, w1h, w1l, y1, nullptr, nullptr, nullptr, 128, 768, 128);
    // 4) temporal attention (2 queries/thread)
    temporal_attn<<<dim3(PP, HD), 64>>>(y1, thi, tlo);
    // 5) QKV2   [launch index 5: ncu capture target]
    gemm_mma<0><<<dim3(768 / TN, ROWS / TM), 256, SMEM_BYTES>>>(
        thi, tlo, w2h, w2l, y2, nullptr, nullptr, nullptr, 256, 768, 256);
    // 6) point attention (2 queries/thread)
    point_attn<<<dim3(NN, HD), 128>>>(y2, pahi, palo);
    // 7) fused FC: out = pa @ W12 + b12
    gemm_mma<0><<<dim3(256 / TN, ROWS / TM), 256, SMEM_BYTES>>>(
        pahi, palo, w12h, w12l, out, nullptr, nullptr, b12, 256, 256, 256);
}

// round 13
// speedup vs baseline: 3.3590x; 1.2523x over previous
#include <cuda_runtime.h>
#include <cuda_bf16.h>
#include <cstdint>

typedef __nv_bfloat16 bf16;
typedef unsigned long long u64;

#define NN 128
#define PP 256
#define DD 128
#define HD 16
#define ROWS (NN*PP)      // 32768
#define HIDDEN 2048

// ---------------- scratch (device globals; no cudaMalloc allowed) ----------
__device__ bf16  g_xhi[(size_t)ROWS * DD],    g_xlo[(size_t)ROWS * DD];
__device__ float g_y1 [(size_t)ROWS * 768];
__device__ bf16  g_thi[(size_t)ROWS * 256],   g_tlo[(size_t)ROWS * 256];
__device__ float g_y2 [(size_t)ROWS * 768];
__device__ bf16  g_pahi[(size_t)ROWS * 256],  g_palo[(size_t)ROWS * 256];
// transposed split weights: Bt[n][k]
__device__ bf16  g_w1t_hi[768 * 128],   g_w1t_lo[768 * 128];
__device__ bf16  g_w2t_hi[768 * 256],   g_w2t_lo[768 * 256];
__device__ bf16  g_f2t_hi[256 * 2048],  g_f2t_lo[256 * 2048];   // fc2_w^T split
__device__ bf16  g_f1a_hi[256 * 2048],  g_f1a_lo[256 * 2048];   // fc1_w row-major split
// fused FC weight: W12T = fc2_w^T @ fc1_w^T (split-K partials, then split)
__device__ float g_w12p[8 * 256 * 256];
__device__ bf16  g_w12h[256 * 256],     g_w12l[256 * 256];
__device__ float g_b12[256];

// ---------------- helpers ---------------------------------------------------
__device__ __forceinline__ uint32_t smem_u32(const void* p) {
    uint32_t a;
    asm("{ .reg .u64 t; cvta.to.shared.u64 t, %1; cvt.u32.u64 %0, t; }"
        : "=r"(a) : "l"(p));
    return a;
}
__device__ __forceinline__ void cp16(uint32_t dst, const void* src) {
    asm volatile("cp.async.cg.shared.global [%0], [%1], 16;"
                 :: "r"(dst), "l"(src) : "memory");
}
__device__ __forceinline__ void mma_bf16(float* d, const uint32_t* a, const uint32_t* b) {
    asm volatile(
        "mma.sync.aligned.m16n8k16.row.col.f32.bf16.bf16.f32 "
        "{%0,%1,%2,%3}, {%4,%5,%6,%7}, {%8,%9}, {%0,%1,%2,%3};"
        : "+f"(d[0]), "+f"(d[1]), "+f"(d[2]), "+f"(d[3])
        : "r"(a[0]), "r"(a[1]), "r"(a[2]), "r"(a[3]), "r"(b[0]), "r"(b[1]));
}
__device__ __forceinline__ void ldsm4(uint32_t& r0, uint32_t& r1, uint32_t& r2,
                                      uint32_t& r3, uint32_t addr) {
    asm volatile("ldmatrix.sync.aligned.m8n8.x4.shared.b16 {%0,%1,%2,%3}, [%4];"
                 : "=r"(r0), "=r"(r1), "=r"(r2), "=r"(r3) : "r"(addr));
}
__device__ __forceinline__ void split1(float v, uint32_t& hb, uint32_t& lb) {
    bf16 h = __float2bfloat16(v);
    bf16 l = __float2bfloat16(v - __bfloat162float(h));
    hb = (uint32_t)__bfloat16_as_ushort(h);
    lb = (uint32_t)__bfloat16_as_ushort(l);
}
// pack two f32 into bf16x2 (even value -> low half)
__device__ __forceinline__ uint32_t packbf(float even, float odd) {
    uint32_t r;
    asm("cvt.rn.bf16x2.f32 %0, %1, %2;" : "=r"(r) : "f"(odd), "f"(even));
    return r;
}
// split pair (even,odd) into hi/lo bf16x2 regs
__device__ __forceinline__ void splitpair(float e, float o, uint32_t& h, uint32_t& l) {
    h = packbf(e, o);
    const float he = __uint_as_float(h << 16);
    const float ho = __uint_as_float(h & 0xffff0000u);
    l = packbf(e - he, o - ho);
}

// ---------------- split-bf16 mma.sync GEMM ---------------------------------
#define TM 128
#define TN 128
#define KC 32
#define ROWB 64
#define OPB (128 * ROWB)
#define STB (4 * OPB)
#define NSTG 3
#define SMEM_BYTES (NSTG * STB)      // 98304

template <int EPI>
__global__ __launch_bounds__(256, 2) void gemm_mma(
    const bf16* __restrict__ Ahi, const bf16* __restrict__ Alo,
    const bf16* __restrict__ Bhi, const bf16* __restrict__ Blo,
    float* __restrict__ C, bf16* __restrict__ Chi, bf16* __restrict__ Clo,
    const float* __restrict__ bias, int K, int ldc, int lda)
{
    extern __shared__ char smem[];
    const uint32_t sb = smem_u32(smem);
    const int tid = threadIdx.x, lane = tid & 31, wid = tid >> 5;
    const int wm = wid >> 2, wn = wid & 3;
    const int bn = blockIdx.x * TN, bm = blockIdx.y * TM;
    const int lr = lane >> 2, lc = lane & 3;
    const int koff = (EPI == 2) ? (int)blockIdx.z * K : 0;

    const int j  = lane >> 3;
    const int rr = ((j & 1) << 3) + (lane & 7);
    const int xr = (rr >> 1) & 3;
    const int cj = j >> 1;
    uint32_t loff[2];
    loff[0] = (uint32_t)(rr * ROWB + (((0 + cj) ^ xr) << 4));
    loff[1] = (uint32_t)(rr * ROWB + (((2 + cj) ^ xr) << 4));

    float acc[4][4][4];
    #pragma unroll
    for (int i = 0; i < 4; i++)
        #pragma unroll
        for (int jj = 0; jj < 4; jj++)
            #pragma unroll
            for (int e = 0; e < 4; e++) acc[i][jj][e] = 0.f;

    const int nc = K / KC;

    auto load_stage = [&](int c) {
        const int buf = c % NSTG;
        const bf16* gs[4] = {
            Ahi + (size_t)bm * lda + koff + c * KC,
            Alo + (size_t)bm * lda + koff + c * KC,
            Bhi + (size_t)bn * lda + koff + c * KC,
            Blo + (size_t)bn * lda + koff + c * KC };
        #pragma unroll
        for (int op = 0; op < 4; op++) {
            #pragma unroll
            for (int l = 0; l < 2; l++) {
                const int idx = tid + l * 256;
                const int r = idx >> 2, c8 = idx & 3;
                const uint32_t dst = sb + buf * STB + op * OPB +
                    (uint32_t)(r * ROWB + ((c8 ^ ((r >> 1) & 3)) << 4));
                cp16(dst, gs[op] + (size_t)r * lda + c8 * 8);
            }
        }
        asm volatile("cp.async.commit_group;" ::: "memory");
    };

    load_stage(0);
    if (nc > 1) load_stage(1);

    for (int c = 0; c < nc; c++) {
        if (c < nc - 1) {
            asm volatile("cp.async.wait_group 1;" ::: "memory");
        } else {
            asm volatile("cp.async.wait_group 0;" ::: "memory");
        }
        __syncthreads();
        if (c + 2 < nc) load_stage(c + 2);

        const uint32_t st = sb + (c % NSTG) * STB;
        const uint32_t aB = st + (uint32_t)(wm * 64 * ROWB);
        const uint32_t bB = st + 2 * OPB + (uint32_t)(wn * 32 * ROWB);

        #pragma unroll
        for (int k16 = 0; k16 < 2; k16++) {
            const uint32_t lo = loff[k16];
            uint32_t bh[4][2], bl[4][2];
            #pragma unroll
            for (int ntp = 0; ntp < 2; ntp++) {
                const uint32_t nb = bB + (uint32_t)(ntp * 16 * ROWB) + lo;
                ldsm4(bh[2*ntp][0], bh[2*ntp+1][0], bh[2*ntp][1], bh[2*ntp+1][1], nb);
                ldsm4(bl[2*ntp][0], bl[2*ntp+1][0], bl[2*ntp][1], bl[2*ntp+1][1], nb + OPB);
            }
            uint32_t ah[2][4], al[2][4];
            ldsm4(ah[0][0], ah[0][1], ah[0][2], ah[0][3], aB + lo);
            ldsm4(al[0][0], al[0][1], al[0][2], al[0][3], aB + OPB + lo);
            #pragma unroll
            for (int mt = 0; mt < 4; mt++) {
                const int cur = mt & 1, nxt = cur ^ 1;
                if (mt < 3) {
                    const uint32_t ab = aB + (uint32_t)((mt + 1) * 16 * ROWB) + lo;
                    ldsm4(ah[nxt][0], ah[nxt][1], ah[nxt][2], ah[nxt][3], ab);
                    ldsm4(al[nxt][0], al[nxt][1], al[nxt][2], al[nxt][3], ab + OPB);
                }
                #pragma unroll
                for (int nt = 0; nt < 4; nt++) {
                    mma_bf16(acc[mt][nt], ah[cur], bh[nt]);
                    mma_bf16(acc[mt][nt], ah[cur], bl[nt]);
                    mma_bf16(acc[mt][nt], al[cur], bh[nt]);
                }
            }
        }
    }

    const size_t zoff = (EPI == 2) ? (size_t)blockIdx.z * 65536 : 0;
    #pragma unroll
    for (int mt = 0; mt < 4; mt++) {
        #pragma unroll
        for (int nt = 0; nt < 4; nt++) {
            const int row = bm + wm * 64 + mt * 16 + lr;
            const int col = bn + wn * 32 + nt * 8 + lc * 2;
            float v0 = acc[mt][nt][0], v1 = acc[mt][nt][1];
            float v2 = acc[mt][nt][2], v3 = acc[mt][nt][3];
            if (EPI == 0 && bias) {
                const float b0 = __ldg(bias + col), b1 = __ldg(bias + col + 1);
                v0 += b0; v1 += b1; v2 += b0; v3 += b1;
            }
            if (EPI != 1) {
                *(float2*)(C + zoff + (size_t)row * ldc + col)       = make_float2(v0, v1);
                *(float2*)(C + zoff + (size_t)(row + 8) * ldc + col) = make_float2(v2, v3);
            } else {
                uint32_t h0, l0, h1, l1;
                splitpair(v0, v1, h0, l0);
                splitpair(v2, v3, h1, l1);
                *(uint32_t*)(Chi + (size_t)row * ldc + col)       = h0;
                *(uint32_t*)(Chi + (size_t)(row + 8) * ldc + col) = h1;
                *(uint32_t*)(Clo + (size_t)row * ldc + col)       = l0;
                *(uint32_t*)(Clo + (size_t)(row + 8) * ldc + col) = l1;
            }
        }
    }
}

// ---------------- fused conversion kernel (ONE launch) ---------------------
__global__ __launch_bounds__(256) void conv_all(
    const float* __restrict__ x, bf16* __restrict__ xhi, bf16* __restrict__ xlo,
    const float* __restrict__ W1, const float* __restrict__ W2,
    const float* __restrict__ fc1w, const float* __restrict__ fc2w,
    const float* __restrict__ fc1b, const float* __restrict__ fc2b,
    bf16* __restrict__ w1h, bf16* __restrict__ w1l,
    bf16* __restrict__ w2h, bf16* __restrict__ w2l,
    bf16* __restrict__ f2h, bf16* __restrict__ f2l,
    bf16* __restrict__ f1ah, bf16* __restrict__ f1al,
    float* __restrict__ b12)
{
    __shared__ float tile[32][33];
    const int tid = threadIdx.x;
    int b = blockIdx.x;

    if (b < 4096) {                       // x split
        const int i = b * 256 + tid;
        float4 v = ((const float4*)x)[i];
        uint32_t h0, l0, h1, l1;
        splitpair(v.x, v.y, h0, l0);
        splitpair(v.z, v.w, h1, l1);
        ((uint2*)xhi)[i] = make_uint2(h0, h1);
        ((uint2*)xlo)[i] = make_uint2(l0, l1);
        return;
    }
    b -= 4096;

    if (b >= 800 && b < 1312) {           // fc1_w elementwise split (512)
        const int i = (b - 800) * 256 + tid;
        float4 v = ((const float4*)fc1w)[i];
        uint32_t h0, l0, h1, l1;
        splitpair(v.x, v.y, h0, l0);
        splitpair(v.z, v.w, h1, l1);
        ((uint2*)f1ah)[i] = make_uint2(h0, h1);
        ((uint2*)f1al)[i] = make_uint2(l0, l1);
        return;
    }
    if (b >= 1312) {                      // b12 (256 blocks, one n each)
        const int n = b - 1312;
        float s = 0.f;
        for (int k = tid; k < HIDDEN; k += 256)
            s += fc1b[k] * fc2w[(size_t)k * 256 + n];
        float* red = &tile[0][0];
        red[tid] = s;
        __syncthreads();
        for (int w = 128; w > 0; w >>= 1) {
            if (tid < w) red[tid] += red[tid + w];
            __syncthreads();
        }
        if (tid == 0) b12[n] = red[0] + fc2b[n];
        return;
    }

    const float* B; bf16 *Th, *Tl;
    int K, N, n_off, out_ld, bx, by;
    if (b < 96) {                          // W1 transpose-split
        const int q = b / 32, r = b % 32;
        B = W1 + (size_t)q * 128 * 256; Th = w1h; Tl = w1l;
        K = 128; N = 256; n_off = q * 256; out_ld = 128;
        bx = r % 8; by = r / 8;
    } else if (b < 288) {                  // W2 transpose-split
        b -= 96;
        const int q = b / 64, r = b % 64;
        B = W2 + (size_t)q * 256 * 256; Th = w2h; Tl = w2l;
        K = 256; N = 256; n_off = q * 256; out_ld = 256;
        bx = r % 8; by = r / 8;
    } else {                               // fc2_w transpose-split (512)
        b -= 288;
        B = fc2w; Th = f2h; Tl = f2l;
        K = 2048; N = 256; n_off = 0; out_ld = 2048;
        bx = b % 8; by = b / 8;
    }

    const int n0 = bx * 32, k0 = by * 32;
    const int tx = tid & 31, ty = tid >> 5;
    #pragma unroll
    for (int i = 0; i < 4; i++) {
        const int r = ty + i * 8;
        tile[r][tx] = B[(size_t)(k0 + r) * N + n0 + tx];
    }
    __syncthreads();
    #pragma unroll
    for (int i = 0; i < 4; i++) {
        const int n = ty + i * 8;
        const float v = tile[tx][n];
        uint32_t hb, lb;
        split1(v, hb, lb);
        const size_t o = (size_t)(n_off + n0 + n) * out_ld + k0 + tx;
        Th[o] = __ushort_as_bfloat16((unsigned short)hb);
        Tl[o] = __ushort_as_bfloat16((unsigned short)lb);
    }
}

// ---------------- W12 partial reduce + split -------------------------------
__global__ __launch_bounds__(256) void w12_reduce_split(
    const float* __restrict__ w12p, bf16* __restrict__ w12h, bf16* __restrict__ w12l)
{
    const int i = blockIdx.x * 256 + threadIdx.x;
    float4 s = ((const float4*)w12p)[i];
    #pragma unroll
    for (int z = 1; z < 8; z++) {
        float4 p = ((const float4*)w12p)[z * 16384 + i];
        s.x += p.x; s.y += p.y; s.z += p.z; s.w += p.w;
    }
    uint32_t h0, l0, h1, l1;
    splitpair(s.x, s.y, h0, l0);
    splitpair(s.z, s.w, h1, l1);
    ((uint2*)w12h)[i] = make_uint2(h0, h1);
    ((uint2*)w12l)[i] = make_uint2(l0, l1);
}

// ---------------- MMA flash attention (no-max streaming softmax) -----------
// Block = (bx, a). TEMP=1: queries i, keys I, row(idx)=idx*256+bx.
//                  TEMP=0: queries j, keys J, row(idx)=bx*256+idx.
// Per block: S = Q(SEQ x16) K^T, P = exp(S), O = P V, out = O / rowsum(P).
// Split-bf16 3-pass for both mma stages. K tiles of 64 keys, double-buffered;
// compute in 32-key halves. V staged TRANSPOSED [d][key] so O-mma uses
// non-trans ldsm.
template <int SEQ, int TEMP>
__global__ __launch_bounds__(256) void attn_mma(
    const float* __restrict__ y, bf16* __restrict__ oH, bf16* __restrict__ oL)
{
    constexpr int QW = SEQ / 8;        // queries per warp
    constexpr int MT = QW / 16;        // m16 tiles per warp
    constexpr int QROW = 48;           // bytes per q/k row (32B data + pad)
    constexpr int VROW = 144;          // bytes per v^T row (128B data + pad)
    constexpr int KHI = 64 * QROW;     // 3072 per K half (hi or lo)
    constexpr int VHI = 16 * VROW;     // 2304 per V half
    constexpr int KVSTR = 2 * KHI + 2 * VHI;   // 10752 per buffer
    constexpr int QB = 2 * SEQ * QROW;
    constexpr int NTILES = SEQ / 64;

    __shared__ char sm[QB + 2 * KVSTR];

    const int bx = blockIdx.x, a = blockIdx.y;
    const int tid = threadIdx.x, lane = tid & 31, w = tid >> 5;
    const uint32_t sb = smem_u32(sm);

    const int j  = lane >> 3;
    const int rr = ((j & 1) << 3) + (lane & 7);
    const int cj = j >> 1;
    const uint32_t qoff = (uint32_t)(rr * QROW + cj * 16);
    const uint32_t voffl = (uint32_t)(rr * VROW + cj * 16);

    auto rowof = [&](int idx) -> size_t {
        return TEMP ? ((size_t)idx * 256 + bx) : ((size_t)bx * 256 + idx);
    };

    // ---- stage Q (once) ----
    if (tid < SEQ) {
        const float* p = y + rowof(tid) * 768 + a * 16;
        uint32_t h[8], l[8];
        #pragma unroll
        for (int c = 0; c < 8; c++) {
            float2 v = *(const float2*)(p + c * 2);
            splitpair(v.x, v.y, h[c], l[c]);
        }
        *(uint4*)(sm + tid * QROW)      = make_uint4(h[0], h[1], h[2], h[3]);
        *(uint4*)(sm + tid * QROW + 16) = make_uint4(h[4], h[5], h[6], h[7]);
        char* ql = sm + SEQ * QROW;
        *(uint4*)(ql + tid * QROW)      = make_uint4(l[0], l[1], l[2], l[3]);
        *(uint4*)(ql + tid * QROW + 16) = make_uint4(l[4], l[5], l[6], l[7]);
    }

    auto stage_kv = [&](int kt, int buf) {
        char* base = sm + QB + buf * KVSTR;
        if (tid < 64) {                    // K rows
            const float* p = y + rowof(kt * 64 + tid) * 768 + a * 16 + 256;
            uint32_t h[8], l[8];
            #pragma unroll
            for (int c = 0; c < 8; c++) {
                float2 v = *(const float2*)(p + c * 2);
                splitpair(v.x, v.y, h[c], l[c]);
            }
            *(uint4*)(base + tid * QROW)      = make_uint4(h[0], h[1], h[2], h[3]);
            *(uint4*)(base + tid * QROW + 16) = make_uint4(h[4], h[5], h[6], h[7]);
            char* kl = base + KHI;
            *(uint4*)(kl + tid * QROW)      = make_uint4(l[0], l[1], l[2], l[3]);
            *(uint4*)(kl + tid * QROW + 16) = make_uint4(l[4], l[5], l[6], l[7]);
        } else if (tid < 128) {            // V rows -> transposed store
            const int key = tid - 64;
            const float* p = y + rowof(kt * 64 + key) * 768 + a * 16 + 512;
            char* vh = base + 2 * KHI;
            char* vl = vh + VHI;
            #pragma unroll
            for (int d = 0; d < 16; d++) {
                uint32_t hb, lb;
                split1(p[d], hb, lb);
                *(unsigned short*)(vh + d * VROW + key * 2) = (unsigned short)hb;
                *(unsigned short*)(vl + d * VROW + key * 2) = (unsigned short)lb;
            }
        }
    };

    stage_kv(0, 0);
    __syncthreads();

    // ---- load persistent Q fragments ----
    uint32_t qh[MT][4], ql[MT][4];
    #pragma unroll
    for (int mt = 0; mt < MT; mt++) {
        const uint32_t ad = sb + (uint32_t)((w * QW + mt * 16) * QROW) + qoff;
        ldsm4(qh[mt][0], qh[mt][1], qh[mt][2], qh[mt][3], ad);
        ldsm4(ql[mt][0], ql[mt][1], ql[mt][2], ql[mt][3], ad + SEQ * QROW);
    }

    float l0[MT], l1[MT], oacc[MT][2][4];
    #pragma unroll
    for (int mt = 0; mt < MT; mt++) {
        l0[mt] = 0.f; l1[mt] = 0.f;
        #pragma unroll
        for (int nv = 0; nv < 2; nv++)
            #pragma unroll
            for (int e = 0; e < 4; e++) oacc[mt][nv][e] = 0.f;
    }

    for (int t = 0; t < NTILES; t++) {
        const uint32_t kb = sb + QB + (t & 1) * KVSTR;
        #pragma unroll
        for (int h32 = 0; h32 < 2; h32++) {
            // K fragments: 4 n8 tiles (32 keys)
            uint32_t kh[4][2], kl[4][2];
            #pragma unroll
            for (int ntp = 0; ntp < 2; ntp++) {
                const uint32_t nb = kb + (uint32_t)((h32 * 32 + ntp * 16) * QROW) + qoff;
                ldsm4(kh[2*ntp][0], kh[2*ntp+1][0], kh[2*ntp][1], kh[2*ntp+1][1], nb);
                ldsm4(kl[2*ntp][0], kl[2*ntp+1][0], kl[2*ntp][1], kl[2*ntp+1][1], nb + KHI);
            }
            // V fragments (transposed layout): 2 k16-chunks x 2 n8(d) tiles
            const uint32_t vb = kb + 2 * KHI;
            uint32_t bvh[2][2][2], bvl[2][2][2];
            #pragma unroll
            for (int kc = 0; kc < 2; kc++) {
                const uint32_t ad = vb + voffl + (uint32_t)(h32 * 64 + kc * 32);
                ldsm4(bvh[kc][0][0], bvh[kc][1][0], bvh[kc][0][1], bvh[kc][1][1], ad);
                ldsm4(bvl[kc][0][0], bvl[kc][1][0], bvl[kc][0][1], bvl[kc][1][1], ad + VHI);
            }
            #pragma unroll
            for (int mt = 0; mt < MT; mt++) {
                float s[4][4];
                #pragma unroll
                for (int nt = 0; nt < 4; nt++)
                    #pragma unroll
                    for (int e = 0; e < 4; e++) s[nt][e] = 0.f;
                #pragma unroll
                for (int nt = 0; nt < 4; nt++) {
                    mma_bf16(s[nt], qh[mt], kh[nt]);
                    mma_bf16(s[nt], qh[mt], kl[nt]);
                    mma_bf16(s[nt], ql[mt], kh[nt]);
                }
                float sl0 = 0.f, sl1 = 0.f;
                #pragma unroll
                for (int nt = 0; nt < 4; nt++) {
                    s[nt][0] = __expf(s[nt][0]);
                    s[nt][1] = __expf(s[nt][1]);
                    s[nt][2] = __expf(s[nt][2]);
                    s[nt][3] = __expf(s[nt][3]);
                    sl0 += s[nt][0] + s[nt][1];
                    sl1 += s[nt][2] + s[nt][3];
                }
                sl0 += __shfl_xor_sync(0xFFFFFFFFu, sl0, 1);
                sl0 += __shfl_xor_sync(0xFFFFFFFFu, sl0, 2);
                sl1 += __shfl_xor_sync(0xFFFFFFFFu, sl1, 1);
                sl1 += __shfl_xor_sync(0xFFFFFFFFu, sl1, 2);
                l0[mt] += sl0; l1[mt] += sl1;
                #pragma unroll
                for (int kc = 0; kc < 2; kc++) {
                    uint32_t ph[4], pl[4];
                    splitpair(s[2*kc][0],   s[2*kc][1],   ph[0], pl[0]);
                    splitpair(s[2*kc][2],   s[2*kc][3],   ph[1], pl[1]);
                    splitpair(s[2*kc+1][0], s[2*kc+1][1], ph[2], pl[2]);
                    splitpair(s[2*kc+1][2], s[2*kc+1][3], ph[3], pl[3]);
                    #pragma unroll
                    for (int nv = 0; nv < 2; nv++) {
                        mma_bf16(oacc[mt][nv], ph, bvh[kc][nv]);
                        mma_bf16(oacc[mt][nv], ph, bvl[kc][nv]);
                        mma_bf16(oacc[mt][nv], pl, bvh[kc][nv]);
                    }
                }
            }
        }
        if (t + 1 < NTILES) stage_kv(t + 1, (t + 1) & 1);
        __syncthreads();
    }

    // ---- epilogue: normalize + split-store ----
    const int lr = lane >> 2, lc = lane & 3;
    #pragma unroll
    for (int mt = 0; mt < MT; mt++) {
        const float inv0 = 1.f / l0[mt];
        const float inv1 = 1.f / l1[mt];
        #pragma unroll
        for (int nv = 0; nv < 2; nv++) {
            const int q0 = w * QW + mt * 16 + lr;
            const int col = a * 16 + nv * 8 + lc * 2;
            uint32_t h, l;
            splitpair(oacc[mt][nv][0] * inv0, oacc[mt][nv][1] * inv0, h, l);
            const size_t off0 = rowof(q0) * 256 + col;
            *(uint32_t*)(oH + off0) = h;
            *(uint32_t*)(oL + off0) = l;
            splitpair(oacc[mt][nv][2] * inv1, oacc[mt][nv][3] * inv1, h, l);
            const size_t off1 = rowof(q0 + 8) * 256 + col;
            *(uint32_t*)(oH + off1) = h;
            *(uint32_t*)(oL + off1) = l;
        }
    }
}

// ---------------------------------------------------------------------------
extern "C" void kernel_launch(void* const* d_in, const int* in_sizes, int n_in,
                              void* d_out, int out_size)
{
    const float* x     = (const float*)d_in[0];
    const float* W1    = (const float*)d_in[1];
    const float* W2    = (const float*)d_in[2];
    const float* fc1_w = (const float*)d_in[3];
    const float* fc1_b = (const float*)d_in[4];
    const float* fc2_w = (const float*)d_in[5];
    const float* fc2_b = (const float*)d_in[6];
    float* out = (float*)d_out;

    bf16 *xhi, *xlo, *thi, *tlo, *pahi, *palo;
    bf16 *w1h, *w1l, *w2h, *w2l, *f2h, *f2l, *f1ah, *f1al, *w12h, *w12l;
    float *y1, *y2, *w12p, *b12;
    cudaGetSymbolAddress((void**)&xhi, g_xhi);   cudaGetSymbolAddress((void**)&xlo, g_xlo);
    cudaGetSymbolAddress((void**)&y1, g_y1);     cudaGetSymbolAddress((void**)&y2, g_y2);
    cudaGetSymbolAddress((void**)&thi, g_thi);   cudaGetSymbolAddress((void**)&tlo, g_tlo);
    cudaGetSymbolAddress((void**)&pahi, g_pahi); cudaGetSymbolAddress((void**)&palo, g_palo);
    cudaGetSymbolAddress((void**)&w1h, g_w1t_hi); cudaGetSymbolAddress((void**)&w1l, g_w1t_lo);
    cudaGetSymbolAddress((void**)&w2h, g_w2t_hi); cudaGetSymbolAddress((void**)&w2l, g_w2t_lo);
    cudaGetSymbolAddress((void**)&f2h, g_f2t_hi); cudaGetSymbolAddress((void**)&f2l, g_f2t_lo);
    cudaGetSymbolAddress((void**)&f1ah, g_f1a_hi); cudaGetSymbolAddress((void**)&f1al, g_f1a_lo);
    cudaGetSymbolAddress((void**)&w12p, g_w12p);
    cudaGetSymbolAddress((void**)&w12h, g_w12h); cudaGetSymbolAddress((void**)&w12l, g_w12l);
    cudaGetSymbolAddress((void**)&b12, g_b12);

    cudaFuncSetAttribute(gemm_mma<0>, cudaFuncAttributeMaxDynamicSharedMemorySize, SMEM_BYTES);
    cudaFuncSetAttribute(gemm_mma<1>, cudaFuncAttributeMaxDynamicSharedMemorySize, SMEM_BYTES);
    cudaFuncSetAttribute(gemm_mma<2>, cudaFuncAttributeMaxDynamicSharedMemorySize, SMEM_BYTES);

    // 0) conversions + b12
    conv_all<<<5664, 256>>>(x, xhi, xlo, W1, W2, fc1_w, fc2_w, fc1_b, fc2_b,
                            w1h, w1l, w2h, w2l, f2h, f2l, f1ah, f1al, b12);
    // 1) W12T = fc2_w^T @ fc1_w^T  (split-K=8 partials)
    gemm_mma<2><<<dim3(2, 2, 8), 256, SMEM_BYTES>>>(
        f2h, f2l, f1ah, f1al, w12p, nullptr, nullptr, nullptr, 256, 256, 2048);
    // 2) reduce partials + split
    w12_reduce_split<<<64, 256>>>(w12p, w12h, w12l);
    // 3) QKV1
    gemm_mma<0><<<dim3(768 / TN, ROWS / TM), 256, SMEM_BYTES>>>(
        xhi, xlo, w1h, w1l, y1, nullptr, nullptr, nullptr, 128, 768, 128);
    // 4) temporal attention (MMA flash)
    attn_mma<128, 1><<<dim3(PP, HD), 256>>>(y1, thi, tlo);
    // 5) QKV2   [launch index 5: ncu capture target]
    gemm_mma<0><<<dim3(768 / TN, ROWS / TM), 256, SMEM_BYTES>>>(
        thi, tlo, w2h, w2l, y2, nullptr, nullptr, nullptr, 256, 768, 256);
    // 6) point attention (MMA flash)
    attn_mma<256, 0><<<dim3(NN, HD), 256>>>(y2, pahi, palo);
    // 7) fused FC: out = pa @ W12 + b12
    gemm_mma<0><<<dim3(256 / TN, ROWS / TM), 256, SMEM_BYTES>>>(
        pahi, palo, w12h, w12l, out, nullptr, nullptr, b12, 256, 256, 256);
}